// round 1
// baseline (speedup 1.0000x reference)
#include <cuda_runtime.h>
#include <math.h>

// ---------------- problem constants ----------------
#define NB 8
#define NL 2048
#define NLP1 2049
#define NH 512           // hidden
#define NHEADS 8
#define HDIM 64
#define NLAYERS 4

// ---------------- scratch (device globals; no allocation) ----------------
__device__ float g_nodes[(size_t)NB * NL * NH];      // 32 MB
__device__ float g_xy   [(size_t)NB * NLP1 * NH];
__device__ float g_q    [(size_t)NB * NLP1 * NH];
__device__ float g_k    [(size_t)NB * NLP1 * NH];
__device__ float g_v    [(size_t)NB * NLP1 * NH];
__device__ float g_att  [(size_t)NB * NL * NH];
__device__ float g_relay[NB * NH];
__device__ float g_attr [NB * NH];

// ---------------- SGEMM: C[M,512] = A[M,512] @ B[512,512] (+epilogue) -----
// EPI 0: + bias[n] + extra[(row%2048)*512+n]   (embedding + pos_emb)
// EPI 1: + bias[n]
// EPI 2: leaky_relu(+ bias[n], 0.2)
#define BM 128
#define BN 128
#define BK 8

template<int EPI>
__global__ __launch_bounds__(256) void sgemm_k(
    const float* __restrict__ A, const float* __restrict__ Bw,
    const float* __restrict__ bias, const float* __restrict__ extra,
    float* __restrict__ C, int M)
{
    const int N = 512, K = 512;
    __shared__ float As[2][BK][BM];
    __shared__ float Bs[2][BK][BN];

    int tid = threadIdx.x;
    int bx = blockIdx.x, by = blockIdx.y;

    int aRow = tid >> 1;             // 0..127
    int aCol = (tid & 1) * 4;        // 0 or 4
    int bRow = tid >> 5;             // 0..7
    int bCol = (tid & 31) * 4;       // 0..124

    int gARow = by * BM + aRow;
    bool aValid = gARow < M;
    const float* Aptr = A + (size_t)(aValid ? gARow : 0) * K;
    const float* Bptr = Bw + (size_t)bRow * N + bx * BN + bCol;

    int tx = tid & 15, ty = tid >> 4;

    float acc[8][8];
#pragma unroll
    for (int i = 0; i < 8; i++)
#pragma unroll
        for (int j = 0; j < 8; j++) acc[i][j] = 0.f;

    float4 aReg = aValid ? *(const float4*)(Aptr + aCol) : make_float4(0,0,0,0);
    float4 bReg = *(const float4*)(Bptr);

    As[0][aCol+0][aRow] = aReg.x;
    As[0][aCol+1][aRow] = aReg.y;
    As[0][aCol+2][aRow] = aReg.z;
    As[0][aCol+3][aRow] = aReg.w;
    *(float4*)&Bs[0][bRow][bCol] = bReg;
    __syncthreads();

    const int KT = K / BK;   // 64
    for (int kt = 0; kt < KT; kt++) {
        int s = kt & 1;
        if (kt + 1 < KT) {
            aReg = aValid ? *(const float4*)(Aptr + (kt+1)*BK + aCol)
                          : make_float4(0,0,0,0);
            bReg = *(const float4*)(Bptr + (size_t)(kt+1)*BK*N);
        }
#pragma unroll
        for (int kk = 0; kk < BK; kk++) {
            float4 a0 = *(const float4*)&As[s][kk][ty*8];
            float4 a1 = *(const float4*)&As[s][kk][ty*8+4];
            float4 b0 = *(const float4*)&Bs[s][kk][tx*8];
            float4 b1 = *(const float4*)&Bs[s][kk][tx*8+4];
            float ar[8] = {a0.x,a0.y,a0.z,a0.w,a1.x,a1.y,a1.z,a1.w};
            float br[8] = {b0.x,b0.y,b0.z,b0.w,b1.x,b1.y,b1.z,b1.w};
#pragma unroll
            for (int i = 0; i < 8; i++)
#pragma unroll
                for (int j = 0; j < 8; j++)
                    acc[i][j] += ar[i] * br[j];
        }
        if (kt + 1 < KT) {
            int s2 = s ^ 1;
            As[s2][aCol+0][aRow] = aReg.x;
            As[s2][aCol+1][aRow] = aReg.y;
            As[s2][aCol+2][aRow] = aReg.z;
            As[s2][aCol+3][aRow] = aReg.w;
            *(float4*)&Bs[s2][bRow][bCol] = bReg;
            __syncthreads();
        }
    }

    int colBase = bx * BN + tx * 8;
#pragma unroll
    for (int i = 0; i < 8; i++) {
        int row = by * BM + ty * 8 + i;
        if (row >= M) continue;
        float* Crow = C + (size_t)row * N;
        int l = row & (NL - 1);   // row % 2048 (only used for EPI 0)
#pragma unroll
        for (int j = 0; j < 8; j += 4) {
            float4 r;
            r.x = acc[i][j+0] + bias[colBase+j+0];
            r.y = acc[i][j+1] + bias[colBase+j+1];
            r.z = acc[i][j+2] + bias[colBase+j+2];
            r.w = acc[i][j+3] + bias[colBase+j+3];
            if (EPI == 0) {
                const float* e = extra + (size_t)l * NH + colBase + j;
                r.x += e[0]; r.y += e[1]; r.z += e[2]; r.w += e[3];
            }
            if (EPI == 2) {
                r.x = r.x > 0.f ? r.x : 0.2f * r.x;
                r.y = r.y > 0.f ? r.y : 0.2f * r.y;
                r.z = r.z > 0.f ? r.z : 0.2f * r.z;
                r.w = r.w > 0.f ? r.w : 0.2f * r.w;
            }
            *(float4*)(Crow + colBase + j) = r;
        }
    }
}

// ---------------- relay = mean over L of embs ----------------
__global__ void relay_mean_k(const float* __restrict__ embs, float* __restrict__ relay)
{
    int b = blockIdx.x, j = threadIdx.x;   // 512 threads
    const float* p = embs + (size_t)b * NL * NH + j;
    float s = 0.f;
#pragma unroll 8
    for (int l = 0; l < NL; l++) s += p[(size_t)l * NH];
    relay[b * NH + j] = s * (1.f / NL);
}

// ---------------- LayerNorm + concat relay row into xy ----------------
__global__ __launch_bounds__(256) void ln_concat_k(
    const float* __restrict__ nodes, const float* __restrict__ relay,
    const float* __restrict__ gamma, const float* __restrict__ beta,
    float* __restrict__ xy)
{
    __shared__ float2 sh[8];
    int row = blockIdx.x;                  // 0..B*2049-1
    int b = row / NLP1, l = row - b * NLP1;
    int tid = threadIdx.x;
    float2* dst = (float2*)(xy + (size_t)row * NH);

    if (l == NL) {                         // relay passthrough (not normalized)
        dst[tid] = ((const float2*)(relay + b * NH))[tid];
        return;
    }
    const float2* src = (const float2*)(nodes + ((size_t)b * NL + l) * NH);
    float2 x = src[tid];
    float2 v = make_float2(x.x + x.y, x.x * x.x + x.y * x.y);
    int lane = tid & 31, w = tid >> 5;
#pragma unroll
    for (int o = 16; o; o >>= 1) {
        v.x += __shfl_xor_sync(0xffffffffu, v.x, o);
        v.y += __shfl_xor_sync(0xffffffffu, v.y, o);
    }
    if (lane == 0) sh[w] = v;
    __syncthreads();
    if (tid == 0) {
        float2 t = sh[0];
#pragma unroll
        for (int i = 1; i < 8; i++) { t.x += sh[i].x; t.y += sh[i].y; }
        sh[0] = t;
    }
    __syncthreads();
    float2 t = sh[0];
    float mu = t.x * (1.f / NH);
    float var = t.y * (1.f / NH) - mu * mu;
    float inv = rsqrtf(var + 1e-6f);
    float2 g = ((const float2*)gamma)[tid];
    float2 bb = ((const float2*)beta)[tid];
    float2 o;
    o.x = (x.x - mu) * inv * g.x + bb.x;
    o.y = (x.y - mu) * inv * g.y + bb.y;
    dst[tid] = o;
}

// ---------------- ring attention: window {l-1,l,l+1,relay}, softmax over 4 ----
__global__ __launch_bounds__(256) void ring_attn_k(
    const float* __restrict__ q, const float* __restrict__ k,
    const float* __restrict__ v, float* __restrict__ att)
{
    int gw = blockIdx.x * 8 + (threadIdx.x >> 5);
    int lane = threadIdx.x & 31;
    int h = gw & 7;
    int l = (gw >> 3) & (NL - 1);
    int b = gw >> 14;                      // / (8*2048)

    size_t base = (size_t)b * NLP1 * NH + (size_t)h * HDIM + lane * 2;
    float2 qv = *(const float2*)(q + base + (size_t)l * NH);

    float2 z = make_float2(0.f, 0.f);
    float2 km = (l > 0)      ? *(const float2*)(k + base + (size_t)(l-1) * NH) : z;
    float2 kc =                *(const float2*)(k + base + (size_t)l     * NH);
    float2 kp = (l < NL - 1) ? *(const float2*)(k + base + (size_t)(l+1) * NH) : z;
    float2 kr =                *(const float2*)(k + base + (size_t)NL    * NH);

    float s0 = qv.x * km.x + qv.y * km.y;
    float s1 = qv.x * kc.x + qv.y * kc.y;
    float s2 = qv.x * kp.x + qv.y * kp.y;
    float s3 = qv.x * kr.x + qv.y * kr.y;
#pragma unroll
    for (int o = 16; o; o >>= 1) {
        s0 += __shfl_xor_sync(0xffffffffu, s0, o);
        s1 += __shfl_xor_sync(0xffffffffu, s1, o);
        s2 += __shfl_xor_sync(0xffffffffu, s2, o);
        s3 += __shfl_xor_sync(0xffffffffu, s3, o);
    }
    const float scale = 0.125f;
    s0 *= scale; s1 *= scale; s2 *= scale; s3 *= scale;
    float m = fmaxf(fmaxf(s0, s1), fmaxf(s2, s3));
    float e0 = __expf(s0 - m), e1 = __expf(s1 - m);
    float e2 = __expf(s2 - m), e3 = __expf(s3 - m);
    float inv = 1.f / (e0 + e1 + e2 + e3);

    float2 vm = (l > 0)      ? *(const float2*)(v + base + (size_t)(l-1) * NH) : z;
    float2 vc =                *(const float2*)(v + base + (size_t)l     * NH);
    float2 vp = (l < NL - 1) ? *(const float2*)(v + base + (size_t)(l+1) * NH) : z;
    float2 vr =                *(const float2*)(v + base + (size_t)NL    * NH);

    float2 o;
    o.x = (e0 * vm.x + e1 * vc.x + e2 * vp.x + e3 * vr.x) * inv;
    o.y = (e0 * vm.y + e1 * vc.y + e2 * vp.y + e3 * vr.y) * inv;
    *(float2*)(att + ((size_t)b * NL + l) * NH + (size_t)h * HDIM + lane * 2) = o;
}

// ---------------- star attention: relay query over all 2049 keys ------------
__global__ __launch_bounds__(256) void star_attn_k(
    const float* __restrict__ q, const float* __restrict__ k,
    const float* __restrict__ v, float* __restrict__ attr)
{
    __shared__ float sq[HDIM];
    __shared__ float sc[NLP1];
    __shared__ float red[8];
    __shared__ float part[4][HDIM];

    int b = blockIdx.x >> 3, h = blockIdx.x & 7;
    int tid = threadIdx.x;
    size_t hb = (size_t)b * NLP1 * NH + (size_t)h * HDIM;

    if (tid < HDIM) sq[tid] = q[hb + (size_t)NL * NH + tid];
    __syncthreads();

    float lmax = -1e30f;
    for (int l = tid; l < NLP1; l += 256) {
        const float4* kp = (const float4*)(k + hb + (size_t)l * NH);
        float d = 0.f;
#pragma unroll
        for (int j = 0; j < HDIM / 4; j++) {
            float4 kk = kp[j];
            d += sq[4*j+0]*kk.x + sq[4*j+1]*kk.y + sq[4*j+2]*kk.z + sq[4*j+3]*kk.w;
        }
        d *= 0.125f;
        sc[l] = d;
        lmax = fmaxf(lmax, d);
    }
    int lane = tid & 31, w = tid >> 5;
#pragma unroll
    for (int o = 16; o; o >>= 1) lmax = fmaxf(lmax, __shfl_xor_sync(0xffffffffu, lmax, o));
    if (lane == 0) red[w] = lmax;
    __syncthreads();
    if (tid == 0) {
        float m = red[0];
#pragma unroll
        for (int i = 1; i < 8; i++) m = fmaxf(m, red[i]);
        red[0] = m;
    }
    __syncthreads();
    float m = red[0];
    __syncthreads();

    float lsum = 0.f;
    for (int l = tid; l < NLP1; l += 256) {
        float e = __expf(sc[l] - m);
        sc[l] = e;
        lsum += e;
    }
#pragma unroll
    for (int o = 16; o; o >>= 1) lsum += __shfl_xor_sync(0xffffffffu, lsum, o);
    if (lane == 0) red[w] = lsum;
    __syncthreads();
    if (tid == 0) {
        float s = 0.f;
#pragma unroll
        for (int i = 0; i < 8; i++) s += red[i];
        red[0] = s;
    }
    __syncthreads();
    float Zinv = 1.f / red[0];

    int d = tid & 63, g = tid >> 6;        // 4 groups x 64 dims
    float acc = 0.f;
    for (int l = g; l < NLP1; l += 4)
        acc += sc[l] * v[hb + (size_t)l * NH + d];
    part[g][d] = acc;
    __syncthreads();
    if (tid < HDIM)
        attr[(size_t)b * NH + h * HDIM + tid] =
            (part[0][tid] + part[1][tid] + part[2][tid] + part[3][tid]) * Zinv;
}

// ---------------- tiny star output GEMM + leaky ----------------
__global__ __launch_bounds__(512) void star_out_k(
    const float* __restrict__ attr, const float* __restrict__ w,
    const float* __restrict__ bias, float* __restrict__ relay)
{
    __shared__ float sa[512];
    int b = blockIdx.x, j = threadIdx.x;
    sa[j] = attr[b * NH + j];
    __syncthreads();
    float acc = 0.f;
#pragma unroll 4
    for (int kk = 0; kk < 512; kk++) acc += sa[kk] * w[kk * 512 + j];
    acc += bias[j];
    relay[b * NH + j] = acc > 0.f ? acc : 0.2f * acc;
}

// ---------------- final: 0.5*(relay + max over L) ----------------
__global__ void final_k(const float* __restrict__ nodes,
                        const float* __restrict__ relay, float* __restrict__ out)
{
    int b = blockIdx.x, j = threadIdx.x;   // 512 threads
    const float* p = nodes + (size_t)b * NL * NH + j;
    float m = -3.4e38f;
#pragma unroll 8
    for (int l = 0; l < NL; l++) m = fmaxf(m, p[(size_t)l * NH]);
    out[b * NH + j] = 0.5f * (relay[b * NH + j] + m);
}

// ---------------- launch ----------------
extern "C" void kernel_launch(void* const* d_in, const int* in_sizes, int n_in,
                              void* d_out, int out_size)
{
    const float* data    = (const float*)d_in[0];
    const float* fc_w    = (const float*)d_in[1];
    const float* fc_b    = (const float*)d_in[2];
    const float* pos_emb = (const float*)d_in[3];
    const float* ln_g    = (const float*)d_in[4];
    const float* ln_b    = (const float*)d_in[5];
    const float* wq      = (const float*)d_in[6];
    const float* wk      = (const float*)d_in[7];
    const float* wv      = (const float*)d_in[8];
    const float* bq      = (const float*)d_in[9];
    const float* bk      = (const float*)d_in[10];
    const float* bv      = (const float*)d_in[11];
    const float* ring_wo = (const float*)d_in[12];
    const float* ring_bo = (const float*)d_in[13];
    const float* star_wo = (const float*)d_in[14];
    const float* star_bo = (const float*)d_in[15];
    float* out = (float*)d_out;

    float *nodes, *xy, *q, *k, *v, *att, *relay, *attr;
    cudaGetSymbolAddress((void**)&nodes, g_nodes);
    cudaGetSymbolAddress((void**)&xy,    g_xy);
    cudaGetSymbolAddress((void**)&q,     g_q);
    cudaGetSymbolAddress((void**)&k,     g_k);
    cudaGetSymbolAddress((void**)&v,     g_v);
    cudaGetSymbolAddress((void**)&att,   g_att);
    cudaGetSymbolAddress((void**)&relay, g_relay);
    cudaGetSymbolAddress((void**)&attr,  g_attr);

    const int M_nodes = NB * NL;     // 16384
    const int M_xy    = NB * NLP1;   // 16392
    dim3 gN(4, (M_nodes + BM - 1) / BM);   // (4,128)
    dim3 gX(4, (M_xy    + BM - 1) / BM);   // (4,129)

    // embeddings + pos_emb, then relay = mean
    sgemm_k<0><<<gN, 256>>>(data, fc_w, fc_b, pos_emb, nodes, M_nodes);
    relay_mean_k<<<NB, NH>>>(nodes, relay);

    for (int i = 0; i < NLAYERS; i++) {
        size_t wOff = (size_t)i * 512 * 512;
        size_t bOff = (size_t)i * 512;

        ln_concat_k<<<NB * NLP1, 256>>>(nodes, relay, ln_g + bOff, ln_b + bOff, xy);

        sgemm_k<1><<<gX, 256>>>(xy, wq + wOff, bq + bOff, nullptr, q, M_xy);
        sgemm_k<1><<<gX, 256>>>(xy, wk + wOff, bk + bOff, nullptr, k, M_xy);
        sgemm_k<1><<<gX, 256>>>(xy, wv + wOff, bv + bOff, nullptr, v, M_xy);

        ring_attn_k<<<NB * NL * NHEADS / 8, 256>>>(q, k, v, att);
        sgemm_k<2><<<gN, 256>>>(att, ring_wo + wOff, ring_bo + bOff, nullptr, nodes, M_nodes);

        star_attn_k<<<NB * NHEADS, 256>>>(q, k, v, attr);
        star_out_k<<<NB, 512>>>(attr, star_wo + wOff, star_bo + bOff, relay);
    }

    final_k<<<NB, NH>>>(nodes, relay, out);
}

// round 3
// speedup vs baseline: 2.2159x; 2.2159x over previous
#include <cuda_runtime.h>
#include <cuda_bf16.h>
#include <math.h>
#include <stdint.h>

// ---------------- problem constants ----------------
#define NB 8
#define NL 2048
#define NLP1 2049
#define NH 512
#define NHEADS 8
#define HDIM 64
#define NLAYERS 4

#define MPAD 16512          // 129*128 row capacity
#define KP 1536             // K' = 3*512 (hi | lo | hi)

// ---------------- scratch (device globals; no allocation) ----------------
__device__ float g_nodes[(size_t)NB * NL * NH];
__device__ float g_q    [(size_t)NB * NLP1 * NH];
__device__ float g_k    [(size_t)NB * NLP1 * NH];
__device__ float g_v    [(size_t)NB * NLP1 * NH];
__device__ float g_relay[NB * NH];
__device__ float g_attr [NB * NH];
__device__ float g_part [(size_t)NB * 32 * NH];
__device__ __align__(16) __nv_bfloat16 g_a2[(size_t)MPAD * KP];        // ~50.7MB
__device__ __align__(16) __nv_bfloat16 g_b2[(size_t)17 * NH * KP];     // 17 weight slots

// =====================================================================
//  low-level helpers
// =====================================================================
__device__ __forceinline__ uint32_t smem_u32(const void* p) {
    uint32_t a;
    asm("{ .reg .u64 t; cvta.to.shared.u64 t, %1; cvt.u32.u64 %0, t; }"
        : "=r"(a) : "l"(p));
    return a;
}

#define CP_ASYNC16(dst, src) \
    asm volatile("cp.async.cg.shared.global [%0], [%1], 16;" \
        :: "r"(dst), "l"(src) : "memory")
#define CP_COMMIT() asm volatile("cp.async.commit_group;" ::: "memory")
#define CP_WAIT(n)  asm volatile("cp.async.wait_group %0;" :: "n"(n) : "memory")

__device__ __forceinline__ void ldsm4(uint32_t* r, uint32_t addr) {
    asm volatile("ldmatrix.sync.aligned.m8n8.x4.shared.b16 {%0,%1,%2,%3}, [%4];"
        : "=r"(r[0]), "=r"(r[1]), "=r"(r[2]), "=r"(r[3]) : "r"(addr));
}

__device__ __forceinline__ void mma16816(float* c, const uint32_t* a, const uint32_t* b) {
    asm volatile("mma.sync.aligned.m16n8k16.row.col.f32.bf16.bf16.f32 "
        "{%0,%1,%2,%3}, {%4,%5,%6,%7}, {%8,%9}, {%0,%1,%2,%3};"
        : "+f"(c[0]), "+f"(c[1]), "+f"(c[2]), "+f"(c[3])
        : "r"(a[0]), "r"(a[1]), "r"(a[2]), "r"(a[3]), "r"(b[0]), "r"(b[1]));
}

// swizzled byte offset within one stage tile: 128 rows x 64B (4 chunks of 16B)
__device__ __forceinline__ uint32_t swz(int row, int chunk) {
    return (uint32_t)(row * 64 + ((chunk ^ ((row >> 1) & 3)) << 4));
}

// hi/lo split helpers
__device__ __forceinline__ void split2(float2 x, __nv_bfloat162& H, __nv_bfloat162& L) {
    __nv_bfloat16 hx = __float2bfloat16(x.x), hy = __float2bfloat16(x.y);
    __nv_bfloat16 lx = __float2bfloat16(x.x - __bfloat162float(hx));
    __nv_bfloat16 ly = __float2bfloat16(x.y - __bfloat162float(hy));
    H = __halves2bfloat162(hx, hy);
    L = __halves2bfloat162(lx, ly);
}

// =====================================================================
//  bf16 mma.sync GEMM: C[M,512] = A2[M,KP] @ B2t[512,KP]^T + epilogue
//  EPI 0: +bias +pos_emb ; 1: +bias ; 2: leaky(+bias)
//  tile 128x128, 8 warps (4M x 2N), kblock 32, 4-stage cp.async
// =====================================================================
#define STG 4
#define STAGE_BYTES 8192          // 128 rows * 64B
#define SMEM_GEMM (2 * STG * STAGE_BYTES)   // 64KB
#define KBLKS (KP / 32)           // 48

template<int EPI>
__global__ void __launch_bounds__(256, 2)
mmagemm(const __nv_bfloat16* __restrict__ A, const __nv_bfloat16* __restrict__ Bt,
        const float* __restrict__ bias, const float* __restrict__ extra,
        float* __restrict__ C, int M)
{
    extern __shared__ char smem[];
    const uint32_t aBase = smem_u32(smem);
    const uint32_t bBase = aBase + STG * STAGE_BYTES;
    const int tid = threadIdx.x, wid = tid >> 5, lane = tid & 31;
    const int nt = blockIdx.x, mt = blockIdx.y;
    const int warpM = wid & 3, warpN = wid >> 2;

    // loader mapping: thread -> (row = tid>>2 [+64], chunk = tid&3)
    const int lrow = tid >> 2, lch = tid & 3;
    const __nv_bfloat16* ag0 = A + (size_t)(mt * 128 + lrow) * KP + lch * 8;
    const __nv_bfloat16* bg0 = Bt + (size_t)(nt * 128 + lrow) * KP + lch * 8;
    const uint32_t sA0 = swz(lrow, lch), sA1 = swz(lrow + 64, lch);

#define LOAD_STAGE(kb, stg) do { \
    const __nv_bfloat16* _ag = ag0 + (kb) * 32; \
    const __nv_bfloat16* _bg = bg0 + (kb) * 32; \
    uint32_t _da = aBase + (stg) * STAGE_BYTES; \
    uint32_t _db = bBase + (stg) * STAGE_BYTES; \
    CP_ASYNC16(_da + sA0, _ag); \
    CP_ASYNC16(_da + sA1, _ag + (size_t)64 * KP); \
    CP_ASYNC16(_db + sA0, _bg); \
    CP_ASYNC16(_db + sA1, _bg + (size_t)64 * KP); \
    CP_COMMIT(); \
} while (0)

    LOAD_STAGE(0, 0);
    LOAD_STAGE(1, 1);
    LOAD_STAGE(2, 2);

    // ldmatrix per-lane bases
    const int lr = lane & 7;
    const int aRowB = warpM * 32 + lr + ((lane >> 3) & 1) * 8;   // + mi*16
    const int aChB  = (lane >> 4);                               // + ks*2
    const int bRowB = warpN * 64 + lr + (lane >> 4) * 8;         // + np*16
    const int bChB  = (lane >> 3) & 1;                           // + ks*2

    float acc[64];
#pragma unroll
    for (int i = 0; i < 64; i++) acc[i] = 0.f;

    for (int kb = 0; kb < KBLKS; kb++) {
        const int stg = kb & 3;
        CP_WAIT(2);
        __syncthreads();
        if (kb + 3 < KBLKS) LOAD_STAGE(kb + 3, (kb + 3) & 3);

        const uint32_t da = aBase + stg * STAGE_BYTES;
        const uint32_t db = bBase + stg * STAGE_BYTES;
#pragma unroll
        for (int ks = 0; ks < 2; ks++) {
            uint32_t af[2][4];
#pragma unroll
            for (int mi = 0; mi < 2; mi++)
                ldsm4(af[mi], da + swz(aRowB + mi * 16, aChB + ks * 2));
#pragma unroll
            for (int np = 0; np < 4; np++) {
                uint32_t bf[4];
                ldsm4(bf, db + swz(bRowB + np * 16, bChB + ks * 2));
#pragma unroll
                for (int mi = 0; mi < 2; mi++) {
                    mma16816(&acc[(mi * 8 + np * 2 + 0) * 4], af[mi], bf + 0);
                    mma16816(&acc[(mi * 8 + np * 2 + 1) * 4], af[mi], bf + 2);
                }
            }
        }
        __syncthreads();
    }

    // epilogue
#pragma unroll
    for (int mi = 0; mi < 2; mi++) {
#pragma unroll
        for (int ntile = 0; ntile < 8; ntile++) {
            const float* c = &acc[(mi * 8 + ntile) * 4];
            int row0 = mt * 128 + warpM * 32 + mi * 16 + (lane >> 2);
            int col  = nt * 128 + warpN * 64 + ntile * 8 + (lane & 3) * 2;
            float b0 = bias[col], b1 = bias[col + 1];
#pragma unroll
            for (int half = 0; half < 2; half++) {
                int row = row0 + half * 8;
                if (row >= M) continue;
                float2 o;
                o.x = c[half * 2 + 0] + b0;
                o.y = c[half * 2 + 1] + b1;
                if (EPI == 0) {
                    const float* e = extra + (size_t)(row & (NL - 1)) * NH + col;
                    o.x += e[0]; o.y += e[1];
                }
                if (EPI == 2) {
                    o.x = o.x > 0.f ? o.x : 0.2f * o.x;
                    o.y = o.y > 0.f ? o.y : 0.2f * o.y;
                }
                *(float2*)(C + (size_t)row * NH + col) = o;
            }
        }
    }
#undef LOAD_STAGE
}

// ---------------- A conversion: fp32 -> [hi|lo|hi] (for `data` only) --------
__global__ __launch_bounds__(256) void convA_k(const float* __restrict__ in,
                                               __nv_bfloat16* __restrict__ out, int M)
{
    int i = blockIdx.x * 256 + threadIdx.x;
    if (i >= M * 256) return;
    int row = i >> 8, c = (i & 255) * 2;
    float2 x = *(const float2*)(in + (size_t)row * NH + c);
    __nv_bfloat162 H, L;
    split2(x, H, L);
    __nv_bfloat16* o = out + (size_t)row * KP;
    *(__nv_bfloat162*)(o + c)        = H;
    *(__nv_bfloat162*)(o + 512 + c)  = L;
    *(__nv_bfloat162*)(o + 1024 + c) = H;
}

// ---------------- weight conversion: W[k][n] -> Bt[n][hi|hi|lo] -------------
__global__ __launch_bounds__(256) void convB_k(const float* __restrict__ W,
                                               __nv_bfloat16* __restrict__ Bt)
{
    __shared__ float t[32][33];
    int k0 = blockIdx.x * 32, n0 = blockIdx.y * 32;
    int tx = threadIdx.x & 31, ty = threadIdx.x >> 5;
#pragma unroll
    for (int i = 0; i < 32; i += 8)
        t[ty + i][tx] = W[(size_t)(k0 + ty + i) * NH + n0 + tx];
    __syncthreads();
#pragma unroll
    for (int i = 0; i < 32; i += 8) {
        int n = n0 + ty + i, k = k0 + tx;
        float x = t[tx][ty + i];
        __nv_bfloat16 h = __float2bfloat16(x);
        __nv_bfloat16 lo = __float2bfloat16(x - __bfloat162float(h));
        __nv_bfloat16* o = Bt + (size_t)n * KP;
        o[k] = h; o[512 + k] = h; o[1024 + k] = lo;
    }
}

// ---------------- relay mean, two-phase ----------------
__global__ void relay_part_k(const float* __restrict__ embs, float* __restrict__ part)
{
    int b = blockIdx.y, ch = blockIdx.x, j = threadIdx.x;
    const float* p = embs + ((size_t)b * NL + ch * 64) * NH + j;
    float s = 0.f;
#pragma unroll 8
    for (int l = 0; l < 64; l++) s += p[(size_t)l * NH];
    part[((size_t)b * 32 + ch) * NH + j] = s;
}
__global__ void relay_fin_k(const float* __restrict__ part, float* __restrict__ relay)
{
    int b = blockIdx.x, j = threadIdx.x;
    float s = 0.f;
#pragma unroll
    for (int c = 0; c < 32; c++) s += part[((size_t)b * 32 + c) * NH + j];
    relay[b * NH + j] = s * (1.f / NL);
}

// ---------------- LayerNorm + concat relay -> a2 (hi/lo fused) --------------
__global__ __launch_bounds__(256) void ln_concat_k(
    const float* __restrict__ nodes, const float* __restrict__ relay,
    const float* __restrict__ gamma, const float* __restrict__ beta,
    __nv_bfloat16* __restrict__ a2)
{
    __shared__ float2 sh[8];
    int row = blockIdx.x;
    int b = row / NLP1, l = row - b * NLP1;
    int tid = threadIdx.x;
    int c = tid * 2;
    __nv_bfloat16* dst = a2 + (size_t)row * KP;

    float2 x;
    if (l == NL) {
        x = ((const float2*)(relay + b * NH))[tid];
        __nv_bfloat162 H, L;
        split2(x, H, L);
        *(__nv_bfloat162*)(dst + c)        = H;
        *(__nv_bfloat162*)(dst + 512 + c)  = L;
        *(__nv_bfloat162*)(dst + 1024 + c) = H;
        return;
    }
    x = ((const float2*)(nodes + ((size_t)b * NL + l) * NH))[tid];
    float2 v = make_float2(x.x + x.y, x.x * x.x + x.y * x.y);
    int lane = tid & 31, w = tid >> 5;
#pragma unroll
    for (int o = 16; o; o >>= 1) {
        v.x += __shfl_xor_sync(0xffffffffu, v.x, o);
        v.y += __shfl_xor_sync(0xffffffffu, v.y, o);
    }
    if (lane == 0) sh[w] = v;
    __syncthreads();
    if (tid == 0) {
        float2 t = sh[0];
#pragma unroll
        for (int i = 1; i < 8; i++) { t.x += sh[i].x; t.y += sh[i].y; }
        sh[0] = t;
    }
    __syncthreads();
    float2 t = sh[0];
    float mu = t.x * (1.f / NH);
    float var = t.y * (1.f / NH) - mu * mu;
    float inv = rsqrtf(var + 1e-6f);
    float2 g = ((const float2*)gamma)[tid];
    float2 bb = ((const float2*)beta)[tid];
    float2 o;
    o.x = (x.x - mu) * inv * g.x + bb.x;
    o.y = (x.y - mu) * inv * g.y + bb.y;
    __nv_bfloat162 H, L;
    split2(o, H, L);
    *(__nv_bfloat162*)(dst + c)        = H;
    *(__nv_bfloat162*)(dst + 512 + c)  = L;
    *(__nv_bfloat162*)(dst + 1024 + c) = H;
}

// ---------------- ring attention -> a2 (hi/lo fused) ----------------
__global__ __launch_bounds__(256) void ring_attn_k(
    const float* __restrict__ q, const float* __restrict__ k,
    const float* __restrict__ v, __nv_bfloat16* __restrict__ a2)
{
    int gw = blockIdx.x * 8 + (threadIdx.x >> 5);
    int lane = threadIdx.x & 31;
    int h = gw & 7;
    int l = (gw >> 3) & (NL - 1);
    int b = gw >> 14;
    size_t base = (size_t)b * NLP1 * NH + (size_t)h * HDIM + lane * 2;
    float2 qv = *(const float2*)(q + base + (size_t)l * NH);
    float2 z = make_float2(0.f, 0.f);
    float2 km = (l > 0)      ? *(const float2*)(k + base + (size_t)(l - 1) * NH) : z;
    float2 kc =                *(const float2*)(k + base + (size_t)l       * NH);
    float2 kp = (l < NL - 1) ? *(const float2*)(k + base + (size_t)(l + 1) * NH) : z;
    float2 kr =                *(const float2*)(k + base + (size_t)NL      * NH);
    float s0 = qv.x * km.x + qv.y * km.y;
    float s1 = qv.x * kc.x + qv.y * kc.y;
    float s2 = qv.x * kp.x + qv.y * kp.y;
    float s3 = qv.x * kr.x + qv.y * kr.y;
#pragma unroll
    for (int o = 16; o; o >>= 1) {
        s0 += __shfl_xor_sync(0xffffffffu, s0, o);
        s1 += __shfl_xor_sync(0xffffffffu, s1, o);
        s2 += __shfl_xor_sync(0xffffffffu, s2, o);
        s3 += __shfl_xor_sync(0xffffffffu, s3, o);
    }
    const float scale = 0.125f;
    s0 *= scale; s1 *= scale; s2 *= scale; s3 *= scale;
    float m = fmaxf(fmaxf(s0, s1), fmaxf(s2, s3));
    float e0 = __expf(s0 - m), e1 = __expf(s1 - m);
    float e2 = __expf(s2 - m), e3 = __expf(s3 - m);
    float inv = 1.f / (e0 + e1 + e2 + e3);
    float2 vm = (l > 0)      ? *(const float2*)(v + base + (size_t)(l - 1) * NH) : z;
    float2 vc =                *(const float2*)(v + base + (size_t)l       * NH);
    float2 vp = (l < NL - 1) ? *(const float2*)(v + base + (size_t)(l + 1) * NH) : z;
    float2 vr =                *(const float2*)(v + base + (size_t)NL      * NH);
    float2 o;
    o.x = (e0 * vm.x + e1 * vc.x + e2 * vp.x + e3 * vr.x) * inv;
    o.y = (e0 * vm.y + e1 * vc.y + e2 * vp.y + e3 * vr.y) * inv;

    int row = b * NL + l;
    int c = h * HDIM + lane * 2;
    __nv_bfloat16* dst = a2 + (size_t)row * KP;
    __nv_bfloat162 H, L;
    split2(o, H, L);
    *(__nv_bfloat162*)(dst + c)        = H;
    *(__nv_bfloat162*)(dst + 512 + c)  = L;
    *(__nv_bfloat162*)(dst + 1024 + c) = H;
}

// ---------------- star attention ----------------
__global__ __launch_bounds__(256) void star_attn_k(
    const float* __restrict__ q, const float* __restrict__ k,
    const float* __restrict__ v, float* __restrict__ attr)
{
    __shared__ float sq[HDIM];
    __shared__ float sc[NLP1];
    __shared__ float red[8];
    __shared__ float part[4][HDIM];
    int b = blockIdx.x >> 3, h = blockIdx.x & 7;
    int tid = threadIdx.x;
    size_t hb = (size_t)b * NLP1 * NH + (size_t)h * HDIM;
    if (tid < HDIM) sq[tid] = q[hb + (size_t)NL * NH + tid];
    __syncthreads();
    float lmax = -1e30f;
    for (int l = tid; l < NLP1; l += 256) {
        const float4* kp = (const float4*)(k + hb + (size_t)l * NH);
        float d = 0.f;
#pragma unroll
        for (int j = 0; j < HDIM / 4; j++) {
            float4 kk = kp[j];
            d += sq[4 * j + 0] * kk.x + sq[4 * j + 1] * kk.y
               + sq[4 * j + 2] * kk.z + sq[4 * j + 3] * kk.w;
        }
        d *= 0.125f;
        sc[l] = d;
        lmax = fmaxf(lmax, d);
    }
    int lane = tid & 31, w = tid >> 5;
#pragma unroll
    for (int o = 16; o; o >>= 1) lmax = fmaxf(lmax, __shfl_xor_sync(0xffffffffu, lmax, o));
    if (lane == 0) red[w] = lmax;
    __syncthreads();
    if (tid == 0) {
        float m = red[0];
#pragma unroll
        for (int i = 1; i < 8; i++) m = fmaxf(m, red[i]);
        red[0] = m;
    }
    __syncthreads();
    float m = red[0];
    __syncthreads();
    float lsum = 0.f;
    for (int l = tid; l < NLP1; l += 256) {
        float e = __expf(sc[l] - m);
        sc[l] = e;
        lsum += e;
    }
#pragma unroll
    for (int o = 16; o; o >>= 1) lsum += __shfl_xor_sync(0xffffffffu, lsum, o);
    if (lane == 0) red[w] = lsum;
    __syncthreads();
    if (tid == 0) {
        float s = 0.f;
#pragma unroll
        for (int i = 0; i < 8; i++) s += red[i];
        red[0] = s;
    }
    __syncthreads();
    float Zinv = 1.f / red[0];
    int d = tid & 63, g = tid >> 6;
    float acc = 0.f;
    for (int l = g; l < NLP1; l += 4)
        acc += sc[l] * v[hb + (size_t)l * NH + d];
    part[g][d] = acc;
    __syncthreads();
    if (tid < HDIM)
        attr[(size_t)b * NH + h * HDIM + tid] =
            (part[0][tid] + part[1][tid] + part[2][tid] + part[3][tid]) * Zinv;
}

// ---------------- tiny star output GEMM + leaky ----------------
__global__ __launch_bounds__(512) void star_out_k(
    const float* __restrict__ attr, const float* __restrict__ w,
    const float* __restrict__ bias, float* __restrict__ relay)
{
    __shared__ float sa[512];
    int b = blockIdx.x, j = threadIdx.x;
    sa[j] = attr[b * NH + j];
    __syncthreads();
    float acc = 0.f;
#pragma unroll 4
    for (int kk = 0; kk < 512; kk++) acc += sa[kk] * w[kk * 512 + j];
    acc += bias[j];
    relay[b * NH + j] = acc > 0.f ? acc : 0.2f * acc;
}

// ---------------- final max, two-phase ----------------
__global__ void final_part_k(const float* __restrict__ nodes, float* __restrict__ part)
{
    int b = blockIdx.y, ch = blockIdx.x, j = threadIdx.x;
    const float* p = nodes + ((size_t)b * NL + ch * 64) * NH + j;
    float m = -3.4e38f;
#pragma unroll 8
    for (int l = 0; l < 64; l++) m = fmaxf(m, p[(size_t)l * NH]);
    part[((size_t)b * 32 + ch) * NH + j] = m;
}
__global__ void final_fin_k(const float* __restrict__ part,
                            const float* __restrict__ relay, float* __restrict__ out)
{
    int b = blockIdx.x, j = threadIdx.x;
    float m = -3.4e38f;
#pragma unroll
    for (int c = 0; c < 32; c++) m = fmaxf(m, part[((size_t)b * 32 + c) * NH + j]);
    out[b * NH + j] = 0.5f * (relay[b * NH + j] + m);
}

// =====================================================================
//  host launch
// =====================================================================
extern "C" void kernel_launch(void* const* d_in, const int* in_sizes, int n_in,
                              void* d_out, int out_size)
{
    const float* data    = (const float*)d_in[0];
    const float* fc_w    = (const float*)d_in[1];
    const float* fc_b    = (const float*)d_in[2];
    const float* pos_emb = (const float*)d_in[3];
    const float* ln_g    = (const float*)d_in[4];
    const float* ln_b    = (const float*)d_in[5];
    const float* wq      = (const float*)d_in[6];
    const float* wk      = (const float*)d_in[7];
    const float* wv      = (const float*)d_in[8];
    const float* bq      = (const float*)d_in[9];
    const float* bk      = (const float*)d_in[10];
    const float* bv      = (const float*)d_in[11];
    const float* ring_wo = (const float*)d_in[12];
    const float* ring_bo = (const float*)d_in[13];
    const float* star_wo = (const float*)d_in[14];
    const float* star_bo = (const float*)d_in[15];
    float* out = (float*)d_out;

    float *nodes, *q, *k, *v, *relay, *attr, *part;
    __nv_bfloat16 *a2, *b2;
    cudaGetSymbolAddress((void**)&nodes, g_nodes);
    cudaGetSymbolAddress((void**)&q,     g_q);
    cudaGetSymbolAddress((void**)&k,     g_k);
    cudaGetSymbolAddress((void**)&v,     g_v);
    cudaGetSymbolAddress((void**)&relay, g_relay);
    cudaGetSymbolAddress((void**)&attr,  g_attr);
    cudaGetSymbolAddress((void**)&part,  g_part);
    cudaGetSymbolAddress((void**)&a2,    g_a2);
    cudaGetSymbolAddress((void**)&b2,    g_b2);

    static bool attr_set = false;
    if (!attr_set) {
        cudaFuncSetAttribute(mmagemm<0>, cudaFuncAttributeMaxDynamicSharedMemorySize, SMEM_GEMM);
        cudaFuncSetAttribute(mmagemm<1>, cudaFuncAttributeMaxDynamicSharedMemorySize, SMEM_GEMM);
        cudaFuncSetAttribute(mmagemm<2>, cudaFuncAttributeMaxDynamicSharedMemorySize, SMEM_GEMM);
        attr_set = true;
    }

    const int M_nodes = NB * NL;     // 16384
    const int M_xy    = NB * NLP1;   // 16392
    dim3 gN(4, (M_nodes + 127) / 128);   // (4,128)
    dim3 gX(4, (M_xy + 127) / 128);      // (4,129)
    dim3 cbg(16, 16);
    const size_t WSLOT = (size_t)NH * KP;

    // ---- all weight conversions up front ----
    convB_k<<<cbg, 256>>>(fc_w, b2);
    for (int i = 0; i < NLAYERS; i++) {
        size_t wOff = (size_t)i * 512 * 512;
        convB_k<<<cbg, 256>>>(wq + wOff,      b2 + (1 + i * 4 + 0) * WSLOT);
        convB_k<<<cbg, 256>>>(wk + wOff,      b2 + (1 + i * 4 + 1) * WSLOT);
        convB_k<<<cbg, 256>>>(wv + wOff,      b2 + (1 + i * 4 + 2) * WSLOT);
        convB_k<<<cbg, 256>>>(ring_wo + wOff, b2 + (1 + i * 4 + 3) * WSLOT);
    }

    // ---- embeddings ----
    convA_k<<<(M_nodes * 256 + 255) / 256, 256>>>(data, a2, M_nodes);
    mmagemm<0><<<gN, 256, SMEM_GEMM>>>(a2, b2, fc_b, pos_emb, nodes, M_nodes);
    relay_part_k<<<dim3(32, NB), NH>>>(nodes, part);
    relay_fin_k<<<NB, NH>>>(part, relay);

    for (int i = 0; i < NLAYERS; i++) {
        size_t bOff = (size_t)i * 512;
        const __nv_bfloat16* Wq = b2 + (1 + i * 4 + 0) * WSLOT;
        const __nv_bfloat16* Wk = b2 + (1 + i * 4 + 1) * WSLOT;
        const __nv_bfloat16* Wv = b2 + (1 + i * 4 + 2) * WSLOT;
        const __nv_bfloat16* Wo = b2 + (1 + i * 4 + 3) * WSLOT;

        ln_concat_k<<<NB * NLP1, 256>>>(nodes, relay, ln_g + bOff, ln_b + bOff, a2);

        mmagemm<1><<<gX, 256, SMEM_GEMM>>>(a2, Wq, bq + bOff, nullptr, q, M_xy);
        mmagemm<1><<<gX, 256, SMEM_GEMM>>>(a2, Wk, bk + bOff, nullptr, k, M_xy);
        mmagemm<1><<<gX, 256, SMEM_GEMM>>>(a2, Wv, bv + bOff, nullptr, v, M_xy);

        ring_attn_k<<<NB * NL * NHEADS / 8, 256>>>(q, k, v, a2);
        mmagemm<2><<<gN, 256, SMEM_GEMM>>>(a2, Wo, ring_bo + bOff, nullptr, nodes, M_nodes);

        star_attn_k<<<NB * NHEADS, 256>>>(q, k, v, attr);
        star_out_k<<<NB, 512>>>(attr, star_wo + (size_t)i * 512 * 512, star_bo + bOff, relay);
    }

    final_part_k<<<dim3(32, NB), NH>>>(nodes, part);
    final_fin_k<<<NB, NH>>>(part, relay, out);
}

// round 5
// speedup vs baseline: 2.9503x; 1.3314x over previous
#include <cuda_runtime.h>
#include <cuda_bf16.h>
#include <math.h>
#include <stdint.h>

// ---------------- problem constants ----------------
#define NB 8
#define NL 2048
#define NLP1 2049
#define NH 512
#define NHEADS 8
#define HDIM 64
#define NLAYERS 4

#define MPAD 16512          // 129*128 row capacity (A padding for cp.async)
#define QS 1536             // fused qkv row stride

// ---------------- scratch (device globals; no allocation) ----------------
__device__ float g_nodes[(size_t)NB * NL * NH];            // 32 MB
__device__ __align__(16) float g_xy [(size_t)MPAD * NH];   // 33 MB (padded)
__device__ float g_qkv [(size_t)NB * NLP1 * QS];           // 100 MB
__device__ __align__(16) float g_att[(size_t)NB * NL * NH];// 32 MB
__device__ __align__(16) float g_a32[(size_t)NB * NL * NH];// 32 MB (rounded data)
__device__ __align__(16) float g_b32[(size_t)(512 + NLAYERS * 2048) * NH]; // 17.8 MB
__device__ float g_relay[NB * NH];
__device__ float g_attr [NB * NH];
__device__ float g_part [(size_t)NB * 32 * NH];

// =====================================================================
//  low-level helpers
// =====================================================================
__device__ __forceinline__ uint32_t smem_u32(const void* p) {
    uint32_t a;
    asm("{ .reg .u64 t; cvta.to.shared.u64 t, %1; cvt.u32.u64 %0, t; }"
        : "=r"(a) : "l"(p));
    return a;
}

#define CP_ASYNC16(dst, src) \
    asm volatile("cp.async.cg.shared.global [%0], [%1], 16;" \
        :: "r"(dst), "l"(src) : "memory")
#define CP_COMMIT() asm volatile("cp.async.commit_group;" ::: "memory")
#define CP_WAIT(n)  asm volatile("cp.async.wait_group %0;" :: "n"(n) : "memory")

__device__ __forceinline__ void ldsm4(uint32_t* r, uint32_t addr) {
    asm volatile("ldmatrix.sync.aligned.m8n8.x4.shared.b16 {%0,%1,%2,%3}, [%4];"
        : "=r"(r[0]), "=r"(r[1]), "=r"(r[2]), "=r"(r[3]) : "r"(addr));
}

__device__ __forceinline__ void mma1688(float* c, const uint32_t* a, const uint32_t* b) {
    asm volatile("mma.sync.aligned.m16n8k8.row.col.f32.tf32.tf32.f32 "
        "{%0,%1,%2,%3}, {%4,%5,%6,%7}, {%8,%9}, {%0,%1,%2,%3};"
        : "+f"(c[0]), "+f"(c[1]), "+f"(c[2]), "+f"(c[3])
        : "r"(a[0]), "r"(a[1]), "r"(a[2]), "r"(a[3]), "r"(b[0]), "r"(b[1]));
}

// tf32 destination must be a .b32 register in PTX
__device__ __forceinline__ float tf32r(float x) {
    uint32_t u;
    asm("cvt.rna.tf32.f32 %0, %1;" : "=r"(u) : "f"(x));
    return __uint_as_float(u);
}
__device__ __forceinline__ float2 tf32r2(float2 x) {
    x.x = tf32r(x.x); x.y = tf32r(x.y); return x;
}

// swizzled byte offset within one stage tile: 128 rows x 64B (4 chunks of 16B)
__device__ __forceinline__ uint32_t swz(int row, int chunk) {
    return (uint32_t)(row * 64 + ((chunk ^ ((row >> 1) & 3)) << 4));
}

// =====================================================================
//  tf32 mma.sync GEMM: C[M, CS-cols] = A[M,512] @ Bt[N,512]^T + epilogue
//  operands pre-rounded to tf32 (RNA). tile 128x128, 8 warps, kblock 16,
//  4-stage cp.async. Bias selected per 512-col segment (QKV fusion).
//  EPI 0: +bias +pos_emb ; 1: +bias ; 2: leaky(+bias)
// =====================================================================
#define STG 4
#define STAGE_BYTES 8192                 // 128 rows * 64B
#define SMEM_GEMM (2 * STG * STAGE_BYTES) // 64KB
#define KBLKS 32                          // 512 / 16

template<int EPI>
__global__ void __launch_bounds__(256, 2)
mmagemm32(const float* __restrict__ A, const float* __restrict__ Bt,
          const float* __restrict__ b0p, const float* __restrict__ b1p,
          const float* __restrict__ b2p, const float* __restrict__ extra,
          float* __restrict__ C, int M, int CS)
{
    extern __shared__ char smem[];
    const uint32_t aBase = smem_u32(smem);
    const uint32_t bBase = aBase + STG * STAGE_BYTES;
    const int tid = threadIdx.x, wid = tid >> 5, lane = tid & 31;
    const int nt = blockIdx.x, mt = blockIdx.y;
    const int warpM = wid & 3, warpN = wid >> 2;

    // loader mapping: thread -> (rows lrow, lrow+64 ; 16B chunk lch)
    const int lrow = tid >> 2, lch = tid & 3;
    const float* ag0 = A + (size_t)(mt * 128 + lrow) * NH + lch * 4;
    const float* bg0 = Bt + (size_t)(nt * 128 + lrow) * NH + lch * 4;
    const uint32_t sA0 = swz(lrow, lch), sA1 = swz(lrow + 64, lch);

#define LOAD_STAGE(kb, stg) do { \
    const float* _ag = ag0 + (kb) * 16; \
    const float* _bg = bg0 + (kb) * 16; \
    uint32_t _da = aBase + (stg) * STAGE_BYTES; \
    uint32_t _db = bBase + (stg) * STAGE_BYTES; \
    CP_ASYNC16(_da + sA0, _ag); \
    CP_ASYNC16(_da + sA1, _ag + (size_t)64 * NH); \
    CP_ASYNC16(_db + sA0, _bg); \
    CP_ASYNC16(_db + sA1, _bg + (size_t)64 * NH); \
    CP_COMMIT(); \
} while (0)

    LOAD_STAGE(0, 0);
    LOAD_STAGE(1, 1);
    LOAD_STAGE(2, 2);

    // ldmatrix per-lane bases (8x4 fp32 tiles viewed as 8x8 b16)
    const int t8 = lane >> 3, lr = lane & 7;
    const int aRowL = warpM * 32 + (t8 & 1) * 8 + lr;   // + mi*16
    const int aChL  = t8 >> 1;                          // + ks*2
    const int bRowL = warpN * 64 + (t8 >> 1) * 8 + lr;  // + p*16
    const int bChL  = t8 & 1;                           // + ks*2

    float acc[64];
#pragma unroll
    for (int i = 0; i < 64; i++) acc[i] = 0.f;

    for (int kb = 0; kb < KBLKS; kb++) {
        const int stg = kb & 3;
        CP_WAIT(2);
        __syncthreads();
        if (kb + 3 < KBLKS) LOAD_STAGE(kb + 3, (kb + 3) & 3);

        const uint32_t da = aBase + stg * STAGE_BYTES;
        const uint32_t db = bBase + stg * STAGE_BYTES;
#pragma unroll
        for (int ks = 0; ks < 2; ks++) {
            uint32_t af[2][4];
#pragma unroll
            for (int mi = 0; mi < 2; mi++)
                ldsm4(af[mi], da + swz(aRowL + mi * 16, ks * 2 + aChL));
#pragma unroll
            for (int p = 0; p < 4; p++) {
                uint32_t bf[4];
                ldsm4(bf, db + swz(bRowL + p * 16, ks * 2 + bChL));
#pragma unroll
                for (int mi = 0; mi < 2; mi++) {
                    mma1688(&acc[(mi * 8 + 2 * p + 0) * 4], af[mi], bf + 0);
                    mma1688(&acc[(mi * 8 + 2 * p + 1) * 4], af[mi], bf + 2);
                }
            }
        }
        __syncthreads();
    }

    // epilogue
#pragma unroll
    for (int mi = 0; mi < 2; mi++) {
#pragma unroll
        for (int ntile = 0; ntile < 8; ntile++) {
            const float* c = &acc[(mi * 8 + ntile) * 4];
            int row0 = mt * 128 + warpM * 32 + mi * 16 + (lane >> 2);
            int col  = nt * 128 + warpN * 64 + ntile * 8 + (lane & 3) * 2;
            int seg = col >> 9;
            const float* bp = (seg == 0) ? b0p : (seg == 1) ? b1p : b2p;
            int cl = col & 511;
            float bb0 = bp[cl], bb1 = bp[cl + 1];
#pragma unroll
            for (int half = 0; half < 2; half++) {
                int row = row0 + half * 8;
                if (row >= M) continue;
                float2 o;
                o.x = c[half * 2 + 0] + bb0;
                o.y = c[half * 2 + 1] + bb1;
                if (EPI == 0) {
                    const float* e = extra + (size_t)(row & (NL - 1)) * NH + col;
                    o.x += e[0]; o.y += e[1];
                }
                if (EPI == 2) {
                    o.x = o.x > 0.f ? o.x : 0.2f * o.x;
                    o.y = o.y > 0.f ? o.y : 0.2f * o.y;
                }
                *(float2*)(C + (size_t)row * CS + col) = o;
            }
        }
    }
#undef LOAD_STAGE
}

// ---------------- A round-copy (for `data` only) ----------------
__global__ __launch_bounds__(256) void convA32_k(const float* __restrict__ in,
                                                 float* __restrict__ out, int n4)
{
    int i = blockIdx.x * 256 + threadIdx.x;
    if (i >= n4) return;
    float4 x = ((const float4*)in)[i];
    x.x = tf32r(x.x); x.y = tf32r(x.y); x.z = tf32r(x.z); x.w = tf32r(x.w);
    ((float4*)out)[i] = x;
}

// ---------------- weight transpose + round: W[k][n] -> Bt[n][k] -------------
__global__ __launch_bounds__(256) void convB32_k(const float* __restrict__ W,
                                                 float* __restrict__ Bt)
{
    __shared__ float t[32][33];
    int k0 = blockIdx.x * 32, n0 = blockIdx.y * 32;
    int tx = threadIdx.x & 31, ty = threadIdx.x >> 5;
#pragma unroll
    for (int i = 0; i < 32; i += 8)
        t[ty + i][tx] = W[(size_t)(k0 + ty + i) * NH + n0 + tx];
    __syncthreads();
#pragma unroll
    for (int i = 0; i < 32; i += 8) {
        int n = n0 + ty + i, k = k0 + tx;
        Bt[(size_t)n * NH + k] = tf32r(t[tx][ty + i]);
    }
}

// ---------------- relay mean, two-phase ----------------
__global__ void relay_part_k(const float* __restrict__ embs, float* __restrict__ part)
{
    int b = blockIdx.y, ch = blockIdx.x, j = threadIdx.x;
    const float* p = embs + ((size_t)b * NL + ch * 64) * NH + j;
    float s = 0.f;
#pragma unroll 8
    for (int l = 0; l < 64; l++) s += p[(size_t)l * NH];
    part[((size_t)b * 32 + ch) * NH + j] = s;
}
__global__ void relay_fin_k(const float* __restrict__ part, float* __restrict__ relay)
{
    int b = blockIdx.x, j = threadIdx.x;
    float s = 0.f;
#pragma unroll
    for (int c = 0; c < 32; c++) s += part[((size_t)b * 32 + c) * NH + j];
    relay[b * NH + j] = s * (1.f / NL);
}

// ---------------- LayerNorm + concat relay -> xy (tf32-rounded) -------------
__global__ __launch_bounds__(256) void ln_concat_k(
    const float* __restrict__ nodes, const float* __restrict__ relay,
    const float* __restrict__ gamma, const float* __restrict__ beta,
    float* __restrict__ xy)
{
    __shared__ float2 sh[8];
    int row = blockIdx.x;
    int b = row / NLP1, l = row - b * NLP1;
    int tid = threadIdx.x;
    float2* dst = (float2*)(xy + (size_t)row * NH);

    if (l == NL) {
        dst[tid] = tf32r2(((const float2*)(relay + b * NH))[tid]);
        return;
    }
    float2 x = ((const float2*)(nodes + ((size_t)b * NL + l) * NH))[tid];
    float2 v = make_float2(x.x + x.y, x.x * x.x + x.y * x.y);
    int lane = tid & 31, w = tid >> 5;
#pragma unroll
    for (int o = 16; o; o >>= 1) {
        v.x += __shfl_xor_sync(0xffffffffu, v.x, o);
        v.y += __shfl_xor_sync(0xffffffffu, v.y, o);
    }
    if (lane == 0) sh[w] = v;
    __syncthreads();
    if (tid == 0) {
        float2 t = sh[0];
#pragma unroll
        for (int i = 1; i < 8; i++) { t.x += sh[i].x; t.y += sh[i].y; }
        sh[0] = t;
    }
    __syncthreads();
    float2 t = sh[0];
    float mu = t.x * (1.f / NH);
    float var = t.y * (1.f / NH) - mu * mu;
    float inv = rsqrtf(var + 1e-6f);
    float2 g = ((const float2*)gamma)[tid];
    float2 bb = ((const float2*)beta)[tid];
    float2 o;
    o.x = (x.x - mu) * inv * g.x + bb.x;
    o.y = (x.y - mu) * inv * g.y + bb.y;
    dst[tid] = tf32r2(o);
}

// ---------------- ring attention (reads fused qkv) -> att (tf32-rounded) ----
__global__ __launch_bounds__(256) void ring_attn_k(
    const float* __restrict__ qkv, float* __restrict__ att)
{
    int gw = blockIdx.x * 8 + (threadIdx.x >> 5);
    int lane = threadIdx.x & 31;
    int h = gw & 7;
    int l = (gw >> 3) & (NL - 1);
    int b = gw >> 14;
    size_t rb = (size_t)b * NLP1 * QS + (size_t)h * HDIM + lane * 2;
    float2 qv = *(const float2*)(qkv + rb + (size_t)l * QS);

    const float* kk = qkv + rb + 512;
    const float* vv = qkv + rb + 1024;
    float2 z = make_float2(0.f, 0.f);
    float2 km = (l > 0)      ? *(const float2*)(kk + (size_t)(l - 1) * QS) : z;
    float2 kc =                *(const float2*)(kk + (size_t)l       * QS);
    float2 kp = (l < NL - 1) ? *(const float2*)(kk + (size_t)(l + 1) * QS) : z;
    float2 kr =                *(const float2*)(kk + (size_t)NL      * QS);
    float s0 = qv.x * km.x + qv.y * km.y;
    float s1 = qv.x * kc.x + qv.y * kc.y;
    float s2 = qv.x * kp.x + qv.y * kp.y;
    float s3 = qv.x * kr.x + qv.y * kr.y;
#pragma unroll
    for (int o = 16; o; o >>= 1) {
        s0 += __shfl_xor_sync(0xffffffffu, s0, o);
        s1 += __shfl_xor_sync(0xffffffffu, s1, o);
        s2 += __shfl_xor_sync(0xffffffffu, s2, o);
        s3 += __shfl_xor_sync(0xffffffffu, s3, o);
    }
    const float scale = 0.125f;
    s0 *= scale; s1 *= scale; s2 *= scale; s3 *= scale;
    float m = fmaxf(fmaxf(s0, s1), fmaxf(s2, s3));
    float e0 = __expf(s0 - m), e1 = __expf(s1 - m);
    float e2 = __expf(s2 - m), e3 = __expf(s3 - m);
    float inv = 1.f / (e0 + e1 + e2 + e3);
    float2 vm = (l > 0)      ? *(const float2*)(vv + (size_t)(l - 1) * QS) : z;
    float2 vc =                *(const float2*)(vv + (size_t)l       * QS);
    float2 vp = (l < NL - 1) ? *(const float2*)(vv + (size_t)(l + 1) * QS) : z;
    float2 vr =                *(const float2*)(vv + (size_t)NL      * QS);
    float2 o;
    o.x = (e0 * vm.x + e1 * vc.x + e2 * vp.x + e3 * vr.x) * inv;
    o.y = (e0 * vm.y + e1 * vc.y + e2 * vp.y + e3 * vr.y) * inv;
    *(float2*)(att + ((size_t)b * NL + l) * NH + (size_t)h * HDIM + lane * 2) = tf32r2(o);
}

// ---------------- star attention (reads fused qkv) ----------------
__global__ __launch_bounds__(256) void star_attn_k(
    const float* __restrict__ qkv, float* __restrict__ attr)
{
    __shared__ float sq[HDIM];
    __shared__ float sc[NLP1];
    __shared__ float red[8];
    __shared__ float part[4][HDIM];
    int b = blockIdx.x >> 3, h = blockIdx.x & 7;
    int tid = threadIdx.x;
    size_t hb = (size_t)b * NLP1 * QS + (size_t)h * HDIM;
    if (tid < HDIM) sq[tid] = qkv[hb + (size_t)NL * QS + tid];   // relay q
    __syncthreads();
    float lmax = -1e30f;
    for (int l = tid; l < NLP1; l += 256) {
        const float4* kp = (const float4*)(qkv + hb + 512 + (size_t)l * QS);
        float d = 0.f;
#pragma unroll
        for (int j = 0; j < HDIM / 4; j++) {
            float4 kk = kp[j];
            d += sq[4 * j + 0] * kk.x + sq[4 * j + 1] * kk.y
               + sq[4 * j + 2] * kk.z + sq[4 * j + 3] * kk.w;
        }
        d *= 0.125f;
        sc[l] = d;
        lmax = fmaxf(lmax, d);
    }
    int lane = tid & 31, w = tid >> 5;
#pragma unroll
    for (int o = 16; o; o >>= 1) lmax = fmaxf(lmax, __shfl_xor_sync(0xffffffffu, lmax, o));
    if (lane == 0) red[w] = lmax;
    __syncthreads();
    if (tid == 0) {
        float m = red[0];
#pragma unroll
        for (int i = 1; i < 8; i++) m = fmaxf(m, red[i]);
        red[0] = m;
    }
    __syncthreads();
    float m = red[0];
    __syncthreads();
    float lsum = 0.f;
    for (int l = tid; l < NLP1; l += 256) {
        float e = __expf(sc[l] - m);
        sc[l] = e;
        lsum += e;
    }
#pragma unroll
    for (int o = 16; o; o >>= 1) lsum += __shfl_xor_sync(0xffffffffu, lsum, o);
    if (lane == 0) red[w] = lsum;
    __syncthreads();
    if (tid == 0) {
        float s = 0.f;
#pragma unroll
        for (int i = 0; i < 8; i++) s += red[i];
        red[0] = s;
    }
    __syncthreads();
    float Zinv = 1.f / red[0];
    int d = tid & 63, g = tid >> 6;
    float acc = 0.f;
    for (int l = g; l < NLP1; l += 4)
        acc += sc[l] * qkv[hb + 1024 + (size_t)l * QS + d];
    part[g][d] = acc;
    __syncthreads();
    if (tid < HDIM)
        attr[(size_t)b * NH + h * HDIM + tid] =
            (part[0][tid] + part[1][tid] + part[2][tid] + part[3][tid]) * Zinv;
}

// ---------------- tiny star output GEMM + leaky ----------------
__global__ __launch_bounds__(512) void star_out_k(
    const float* __restrict__ attr, const float* __restrict__ w,
    const float* __restrict__ bias, float* __restrict__ relay)
{
    __shared__ float sa[512];
    int b = blockIdx.x, j = threadIdx.x;
    sa[j] = attr[b * NH + j];
    __syncthreads();
    float acc = 0.f;
#pragma unroll 4
    for (int kk = 0; kk < 512; kk++) acc += sa[kk] * w[kk * 512 + j];
    acc += bias[j];
    relay[b * NH + j] = acc > 0.f ? acc : 0.2f * acc;
}

// ---------------- final max, two-phase ----------------
__global__ void final_part_k(const float* __restrict__ nodes, float* __restrict__ part)
{
    int b = blockIdx.y, ch = blockIdx.x, j = threadIdx.x;
    const float* p = nodes + ((size_t)b * NL + ch * 64) * NH + j;
    float m = -3.4e38f;
#pragma unroll 8
    for (int l = 0; l < 64; l++) m = fmaxf(m, p[(size_t)l * NH]);
    part[((size_t)b * 32 + ch) * NH + j] = m;
}
__global__ void final_fin_k(const float* __restrict__ part,
                            const float* __restrict__ relay, float* __restrict__ out)
{
    int b = blockIdx.x, j = threadIdx.x;
    float m = -3.4e38f;
#pragma unroll
    for (int c = 0; c < 32; c++) m = fmaxf(m, part[((size_t)b * 32 + c) * NH + j]);
    out[b * NH + j] = 0.5f * (relay[b * NH + j] + m);
}

// =====================================================================
//  host launch
// =====================================================================
extern "C" void kernel_launch(void* const* d_in, const int* in_sizes, int n_in,
                              void* d_out, int out_size)
{
    const float* data    = (const float*)d_in[0];
    const float* fc_w    = (const float*)d_in[1];
    const float* fc_b    = (const float*)d_in[2];
    const float* pos_emb = (const float*)d_in[3];
    const float* ln_g    = (const float*)d_in[4];
    const float* ln_b    = (const float*)d_in[5];
    const float* wq      = (const float*)d_in[6];
    const float* wk      = (const float*)d_in[7];
    const float* wv      = (const float*)d_in[8];
    const float* bq      = (const float*)d_in[9];
    const float* bk      = (const float*)d_in[10];
    const float* bv      = (const float*)d_in[11];
    const float* ring_wo = (const float*)d_in[12];
    const float* ring_bo = (const float*)d_in[13];
    const float* star_wo = (const float*)d_in[14];
    const float* star_bo = (const float*)d_in[15];
    float* out = (float*)d_out;

    float *nodes, *xy, *qkv, *att, *a32, *b32, *relay, *attr, *part;
    cudaGetSymbolAddress((void**)&nodes, g_nodes);
    cudaGetSymbolAddress((void**)&xy,    g_xy);
    cudaGetSymbolAddress((void**)&qkv,   g_qkv);
    cudaGetSymbolAddress((void**)&att,   g_att);
    cudaGetSymbolAddress((void**)&a32,   g_a32);
    cudaGetSymbolAddress((void**)&b32,   g_b32);
    cudaGetSymbolAddress((void**)&relay, g_relay);
    cudaGetSymbolAddress((void**)&attr,  g_attr);
    cudaGetSymbolAddress((void**)&part,  g_part);

    static bool attr_set = false;
    if (!attr_set) {
        cudaFuncSetAttribute(mmagemm32<0>, cudaFuncAttributeMaxDynamicSharedMemorySize, SMEM_GEMM);
        cudaFuncSetAttribute(mmagemm32<1>, cudaFuncAttributeMaxDynamicSharedMemorySize, SMEM_GEMM);
        cudaFuncSetAttribute(mmagemm32<2>, cudaFuncAttributeMaxDynamicSharedMemorySize, SMEM_GEMM);
        attr_set = true;
    }

    const int M_nodes = NB * NL;     // 16384
    const int M_xy    = NB * NLP1;   // 16392
    dim3 gN(4, M_nodes / 128);       // (4,128)  N=512
    dim3 gQKV(12, (M_xy + 127) / 128); // (12,129) N=1536
    dim3 cbg(16, 16);

    // b32 layout (rows of 512 floats):
    //   [0,512)   : fc_w^T
    //   layer i   : QKV at rowbase 512 + i*2048 (wq|wk|wv, 512 rows each)
    //               ring at rowbase 512 + i*2048 + 1536
    float* bFC = b32;
    // ---- all weight conversions up front ----
    convB32_k<<<cbg, 256>>>(fc_w, bFC);
    for (int i = 0; i < NLAYERS; i++) {
        size_t wOff = (size_t)i * 512 * 512;
        float* slot = b32 + (size_t)(512 + i * 2048) * NH;
        convB32_k<<<cbg, 256>>>(wq + wOff,      slot);
        convB32_k<<<cbg, 256>>>(wk + wOff,      slot + (size_t)512 * NH);
        convB32_k<<<cbg, 256>>>(wv + wOff,      slot + (size_t)1024 * NH);
        convB32_k<<<cbg, 256>>>(ring_wo + wOff, slot + (size_t)1536 * NH);
    }

    // ---- embeddings ----
    convA32_k<<<(M_nodes * 128 + 255) / 256, 256>>>(data, a32, M_nodes * 128);
    mmagemm32<0><<<gN, 256, SMEM_GEMM>>>(a32, bFC, fc_b, fc_b, fc_b, pos_emb,
                                         nodes, M_nodes, NH);
    relay_part_k<<<dim3(32, NB), NH>>>(nodes, part);
    relay_fin_k<<<NB, NH>>>(part, relay);

    for (int i = 0; i < NLAYERS; i++) {
        size_t bOff = (size_t)i * 512;
        float* slot  = b32 + (size_t)(512 + i * 2048) * NH;
        float* slotO = slot + (size_t)1536 * NH;

        ln_concat_k<<<NB * NLP1, 256>>>(nodes, relay, ln_g + bOff, ln_b + bOff, xy);

        mmagemm32<1><<<gQKV, 256, SMEM_GEMM>>>(xy, slot, bq + bOff, bk + bOff,
                                               bv + bOff, nullptr, qkv, M_xy, QS);

        ring_attn_k<<<NB * NL * NHEADS / 8, 256>>>(qkv, att);
        mmagemm32<2><<<gN, 256, SMEM_GEMM>>>(att, slotO, ring_bo + bOff, ring_bo + bOff,
                                             ring_bo + bOff, nullptr, nodes, M_nodes, NH);

        star_attn_k<<<NB * NHEADS, 256>>>(qkv, attr);
        star_out_k<<<NB, 512>>>(attr, star_wo + (size_t)i * 512 * 512, star_bo + bOff, relay);
    }

    final_part_k<<<dim3(32, NB), NH>>>(nodes, part);
    final_fin_k<<<NB, NH>>>(part, relay, out);
}

// round 6
// speedup vs baseline: 4.0519x; 1.3734x over previous
#include <cuda_runtime.h>
#include <cuda_bf16.h>
#include <math.h>
#include <stdint.h>

// ---------------- problem constants ----------------
#define NB 8
#define NL 2048
#define NLP1 2049
#define NH 512
#define NHEADS 8
#define HDIM 64
#define NLAYERS 4

#define MPAD 16512          // 129*128 row capacity (A padding for cp.async)
#define QS 1536             // fused qkv row stride

// ---------------- scratch (device globals; no allocation) ----------------
__device__ float g_nodes[(size_t)NB * NL * NH];            // 32 MB
__device__ __align__(16) float g_xy [(size_t)MPAD * NH];   // 33 MB (padded)
__device__ float g_qkv [(size_t)NB * NLP1 * QS];           // 100 MB
__device__ __align__(16) float g_att[(size_t)NB * NL * NH];// 32 MB
__device__ __align__(16) float g_a32[(size_t)NB * NL * NH];// 32 MB (rounded data)
__device__ __align__(16) float g_b32[(size_t)(512 + NLAYERS * 2048) * NH]; // 17.8 MB
__device__ float g_relay[NB * NH];
__device__ float g_attr [NB * NH];
__device__ float g_part [(size_t)NB * 32 * NH];

// =====================================================================
//  low-level helpers
// =====================================================================
__device__ __forceinline__ uint32_t smem_u32(const void* p) {
    uint32_t a;
    asm("{ .reg .u64 t; cvta.to.shared.u64 t, %1; cvt.u32.u64 %0, t; }"
        : "=r"(a) : "l"(p));
    return a;
}

#define CP_ASYNC16(dst, src) \
    asm volatile("cp.async.cg.shared.global [%0], [%1], 16;" \
        :: "r"(dst), "l"(src) : "memory")
#define CP_COMMIT() asm volatile("cp.async.commit_group;" ::: "memory")
#define CP_WAIT(n)  asm volatile("cp.async.wait_group %0;" :: "n"(n) : "memory")

__device__ __forceinline__ void ldsm4(uint32_t* r, uint32_t addr) {
    asm volatile("ldmatrix.sync.aligned.m8n8.x4.shared.b16 {%0,%1,%2,%3}, [%4];"
        : "=r"(r[0]), "=r"(r[1]), "=r"(r[2]), "=r"(r[3]) : "r"(addr));
}

__device__ __forceinline__ void mma1688(float* c, const uint32_t* a, const uint32_t* b) {
    asm volatile("mma.sync.aligned.m16n8k8.row.col.f32.tf32.tf32.f32 "
        "{%0,%1,%2,%3}, {%4,%5,%6,%7}, {%8,%9}, {%0,%1,%2,%3};"
        : "+f"(c[0]), "+f"(c[1]), "+f"(c[2]), "+f"(c[3])
        : "r"(a[0]), "r"(a[1]), "r"(a[2]), "r"(a[3]), "r"(b[0]), "r"(b[1]));
}

// tf32 destination must be a .b32 register in PTX
__device__ __forceinline__ float tf32r(float x) {
    uint32_t u;
    asm("cvt.rna.tf32.f32 %0, %1;" : "=r"(u) : "f"(x));
    return __uint_as_float(u);
}
__device__ __forceinline__ float2 tf32r2(float2 x) {
    x.x = tf32r(x.x); x.y = tf32r(x.y); return x;
}

// swizzled byte offset within one stage tile: 128 rows x 64B (4 chunks of 16B)
__device__ __forceinline__ uint32_t swz(int row, int chunk) {
    return (uint32_t)(row * 64 + ((chunk ^ ((row >> 1) & 3)) << 4));
}

// =====================================================================
//  tf32 mma.sync GEMM: C[M, CS-cols] = A[M,512] @ Bt[N,512]^T + epilogue
//  operands pre-rounded to tf32 (RNA). tile 128x128, 8 warps, kblock 16,
//  4-stage cp.async. Bias selected per 512-col segment (QKV fusion).
//  EPI 0: +bias +pos_emb ; 1: +bias ; 2: leaky(+bias)
// =====================================================================
#define STG 4
#define STAGE_BYTES 8192                 // 128 rows * 64B
#define SMEM_GEMM (2 * STG * STAGE_BYTES) // 64KB
#define KBLKS 32                          // 512 / 16

template<int EPI>
__global__ void __launch_bounds__(256, 2)
mmagemm32(const float* __restrict__ A, const float* __restrict__ Bt,
          const float* __restrict__ b0p, const float* __restrict__ b1p,
          const float* __restrict__ b2p, const float* __restrict__ extra,
          float* __restrict__ C, int M, int CS)
{
    extern __shared__ char smem[];
    const uint32_t aBase = smem_u32(smem);
    const uint32_t bBase = aBase + STG * STAGE_BYTES;
    const int tid = threadIdx.x, wid = tid >> 5, lane = tid & 31;
    const int nt = blockIdx.x, mt = blockIdx.y;
    const int warpM = wid & 3, warpN = wid >> 2;

    // loader mapping: thread -> (rows lrow, lrow+64 ; 16B chunk lch)
    const int lrow = tid >> 2, lch = tid & 3;
    const float* ag0 = A + (size_t)(mt * 128 + lrow) * NH + lch * 4;
    const float* bg0 = Bt + (size_t)(nt * 128 + lrow) * NH + lch * 4;
    const uint32_t sA0 = swz(lrow, lch), sA1 = swz(lrow + 64, lch);

#define LOAD_STAGE(kb, stg) do { \
    const float* _ag = ag0 + (kb) * 16; \
    const float* _bg = bg0 + (kb) * 16; \
    uint32_t _da = aBase + (stg) * STAGE_BYTES; \
    uint32_t _db = bBase + (stg) * STAGE_BYTES; \
    CP_ASYNC16(_da + sA0, _ag); \
    CP_ASYNC16(_da + sA1, _ag + (size_t)64 * NH); \
    CP_ASYNC16(_db + sA0, _bg); \
    CP_ASYNC16(_db + sA1, _bg + (size_t)64 * NH); \
    CP_COMMIT(); \
} while (0)

    LOAD_STAGE(0, 0);
    LOAD_STAGE(1, 1);
    LOAD_STAGE(2, 2);

    // ldmatrix per-lane bases (8x4 fp32 tiles viewed as 8x8 b16)
    const int t8 = lane >> 3, lr = lane & 7;
    const int aRowL = warpM * 32 + (t8 & 1) * 8 + lr;   // + mi*16
    const int aChL  = t8 >> 1;                          // + ks*2
    const int bRowL = warpN * 64 + (t8 >> 1) * 8 + lr;  // + p*16
    const int bChL  = t8 & 1;                           // + ks*2

    float acc[64];
#pragma unroll
    for (int i = 0; i < 64; i++) acc[i] = 0.f;

    for (int kb = 0; kb < KBLKS; kb++) {
        const int stg = kb & 3;
        CP_WAIT(2);
        __syncthreads();
        if (kb + 3 < KBLKS) LOAD_STAGE(kb + 3, (kb + 3) & 3);

        const uint32_t da = aBase + stg * STAGE_BYTES;
        const uint32_t db = bBase + stg * STAGE_BYTES;
#pragma unroll
        for (int ks = 0; ks < 2; ks++) {
            uint32_t af[2][4];
#pragma unroll
            for (int mi = 0; mi < 2; mi++)
                ldsm4(af[mi], da + swz(aRowL + mi * 16, ks * 2 + aChL));
#pragma unroll
            for (int p = 0; p < 4; p++) {
                uint32_t bf[4];
                ldsm4(bf, db + swz(bRowL + p * 16, ks * 2 + bChL));
#pragma unroll
                for (int mi = 0; mi < 2; mi++) {
                    mma1688(&acc[(mi * 8 + 2 * p + 0) * 4], af[mi], bf + 0);
                    mma1688(&acc[(mi * 8 + 2 * p + 1) * 4], af[mi], bf + 2);
                }
            }
        }
        __syncthreads();
    }

    // epilogue
#pragma unroll
    for (int mi = 0; mi < 2; mi++) {
#pragma unroll
        for (int ntile = 0; ntile < 8; ntile++) {
            const float* c = &acc[(mi * 8 + ntile) * 4];
            int row0 = mt * 128 + warpM * 32 + mi * 16 + (lane >> 2);
            int col  = nt * 128 + warpN * 64 + ntile * 8 + (lane & 3) * 2;
            int seg = col >> 9;
            const float* bp = (seg == 0) ? b0p : (seg == 1) ? b1p : b2p;
            int cl = col & 511;
            float bb0 = bp[cl], bb1 = bp[cl + 1];
#pragma unroll
            for (int half = 0; half < 2; half++) {
                int row = row0 + half * 8;
                if (row >= M) continue;
                float2 o;
                o.x = c[half * 2 + 0] + bb0;
                o.y = c[half * 2 + 1] + bb1;
                if (EPI == 0) {
                    const float* e = extra + (size_t)(row & (NL - 1)) * NH + col;
                    o.x += e[0]; o.y += e[1];
                }
                if (EPI == 2) {
                    o.x = o.x > 0.f ? o.x : 0.2f * o.x;
                    o.y = o.y > 0.f ? o.y : 0.2f * o.y;
                }
                *(float2*)(C + (size_t)row * CS + col) = o;
            }
        }
    }
#undef LOAD_STAGE
}

// ---------------- A round-copy (for `data` only) ----------------
__global__ __launch_bounds__(256) void convA32_k(const float* __restrict__ in,
                                                 float* __restrict__ out, int n4)
{
    int i = blockIdx.x * 256 + threadIdx.x;
    if (i >= n4) return;
    float4 x = ((const float4*)in)[i];
    x.x = tf32r(x.x); x.y = tf32r(x.y); x.z = tf32r(x.z); x.w = tf32r(x.w);
    ((float4*)out)[i] = x;
}

// ---------------- ALL weight transposes + round in ONE launch ---------------
// slot z: 0 = fc_w -> b32[0]; z=1+i*4+j: layer i, j in {q,k,v,o}
__global__ __launch_bounds__(256) void convB_all_k(
    const float* __restrict__ fc_w, const float* __restrict__ wq,
    const float* __restrict__ wk,   const float* __restrict__ wv,
    const float* __restrict__ wo,   float* __restrict__ b32)
{
    __shared__ float t[32][33];
    int s = blockIdx.z;
    const float* W;
    float* Bt;
    if (s == 0) {
        W = fc_w; Bt = b32;
    } else {
        int i = (s - 1) >> 2, j = (s - 1) & 3;
        const float* src = (j == 0) ? wq : (j == 1) ? wk : (j == 2) ? wv : wo;
        W  = src + (size_t)i * NH * NH;
        Bt = b32 + (size_t)(512 + i * 2048 + j * 512) * NH;
    }
    int k0 = blockIdx.x * 32, n0 = blockIdx.y * 32;
    int tx = threadIdx.x & 31, ty = threadIdx.x >> 5;
#pragma unroll
    for (int i = 0; i < 32; i += 8)
        t[ty + i][tx] = W[(size_t)(k0 + ty + i) * NH + n0 + tx];
    __syncthreads();
#pragma unroll
    for (int i = 0; i < 32; i += 8) {
        int n = n0 + ty + i, k = k0 + tx;
        Bt[(size_t)n * NH + k] = tf32r(t[tx][ty + i]);
    }
}

// ---------------- relay mean, two-phase ----------------
__global__ void relay_part_k(const float* __restrict__ embs, float* __restrict__ part)
{
    int b = blockIdx.y, ch = blockIdx.x, j = threadIdx.x;
    const float* p = embs + ((size_t)b * NL + ch * 64) * NH + j;
    float s = 0.f;
#pragma unroll 8
    for (int l = 0; l < 64; l++) s += p[(size_t)l * NH];
    part[((size_t)b * 32 + ch) * NH + j] = s;
}
__global__ void relay_fin_k(const float* __restrict__ part, float* __restrict__ relay)
{
    int b = blockIdx.x, j = threadIdx.x;
    float s = 0.f;
#pragma unroll
    for (int c = 0; c < 32; c++) s += part[((size_t)b * 32 + c) * NH + j];
    relay[b * NH + j] = s * (1.f / NL);
}

// ---------------- LayerNorm + concat relay -> xy (tf32-rounded) -------------
__global__ __launch_bounds__(256) void ln_concat_k(
    const float* __restrict__ nodes, const float* __restrict__ relay,
    const float* __restrict__ gamma, const float* __restrict__ beta,
    float* __restrict__ xy)
{
    __shared__ float2 sh[8];
    int row = blockIdx.x;
    int b = row / NLP1, l = row - b * NLP1;
    int tid = threadIdx.x;
    float2* dst = (float2*)(xy + (size_t)row * NH);

    if (l == NL) {
        dst[tid] = tf32r2(((const float2*)(relay + b * NH))[tid]);
        return;
    }
    float2 x = ((const float2*)(nodes + ((size_t)b * NL + l) * NH))[tid];
    float2 v = make_float2(x.x + x.y, x.x * x.x + x.y * x.y);
    int lane = tid & 31, w = tid >> 5;
#pragma unroll
    for (int o = 16; o; o >>= 1) {
        v.x += __shfl_xor_sync(0xffffffffu, v.x, o);
        v.y += __shfl_xor_sync(0xffffffffu, v.y, o);
    }
    if (lane == 0) sh[w] = v;
    __syncthreads();
    if (tid == 0) {
        float2 t = sh[0];
#pragma unroll
        for (int i = 1; i < 8; i++) { t.x += sh[i].x; t.y += sh[i].y; }
        sh[0] = t;
    }
    __syncthreads();
    float2 t = sh[0];
    float mu = t.x * (1.f / NH);
    float var = t.y * (1.f / NH) - mu * mu;
    float inv = rsqrtf(var + 1e-6f);
    float2 g = ((const float2*)gamma)[tid];
    float2 bb = ((const float2*)beta)[tid];
    float2 o;
    o.x = (x.x - mu) * inv * g.x + bb.x;
    o.y = (x.y - mu) * inv * g.y + bb.y;
    dst[tid] = tf32r2(o);
}

// ---------------- ring attention (reads fused qkv) -> att (tf32-rounded) ----
__global__ __launch_bounds__(256) void ring_attn_k(
    const float* __restrict__ qkv, float* __restrict__ att)
{
    int gw = blockIdx.x * 8 + (threadIdx.x >> 5);
    int lane = threadIdx.x & 31;
    int h = gw & 7;
    int l = (gw >> 3) & (NL - 1);
    int b = gw >> 14;
    size_t rb = (size_t)b * NLP1 * QS + (size_t)h * HDIM + lane * 2;
    float2 qv = *(const float2*)(qkv + rb + (size_t)l * QS);

    const float* kk = qkv + rb + 512;
    const float* vv = qkv + rb + 1024;
    float2 z = make_float2(0.f, 0.f);
    float2 km = (l > 0)      ? *(const float2*)(kk + (size_t)(l - 1) * QS) : z;
    float2 kc =                *(const float2*)(kk + (size_t)l       * QS);
    float2 kp = (l < NL - 1) ? *(const float2*)(kk + (size_t)(l + 1) * QS) : z;
    float2 kr =                *(const float2*)(kk + (size_t)NL      * QS);
    float s0 = qv.x * km.x + qv.y * km.y;
    float s1 = qv.x * kc.x + qv.y * kc.y;
    float s2 = qv.x * kp.x + qv.y * kp.y;
    float s3 = qv.x * kr.x + qv.y * kr.y;
#pragma unroll
    for (int o = 16; o; o >>= 1) {
        s0 += __shfl_xor_sync(0xffffffffu, s0, o);
        s1 += __shfl_xor_sync(0xffffffffu, s1, o);
        s2 += __shfl_xor_sync(0xffffffffu, s2, o);
        s3 += __shfl_xor_sync(0xffffffffu, s3, o);
    }
    const float scale = 0.125f;
    s0 *= scale; s1 *= scale; s2 *= scale; s3 *= scale;
    float m = fmaxf(fmaxf(s0, s1), fmaxf(s2, s3));
    float e0 = __expf(s0 - m), e1 = __expf(s1 - m);
    float e2 = __expf(s2 - m), e3 = __expf(s3 - m);
    float inv = 1.f / (e0 + e1 + e2 + e3);
    float2 vm = (l > 0)      ? *(const float2*)(vv + (size_t)(l - 1) * QS) : z;
    float2 vc =                *(const float2*)(vv + (size_t)l       * QS);
    float2 vp = (l < NL - 1) ? *(const float2*)(vv + (size_t)(l + 1) * QS) : z;
    float2 vr =                *(const float2*)(vv + (size_t)NL      * QS);
    float2 o;
    o.x = (e0 * vm.x + e1 * vc.x + e2 * vp.x + e3 * vr.x) * inv;
    o.y = (e0 * vm.y + e1 * vc.y + e2 * vp.y + e3 * vr.y) * inv;
    *(float2*)(att + ((size_t)b * NL + l) * NH + (size_t)h * HDIM + lane * 2) = tf32r2(o);
}

// ---------------- star attention (reads fused qkv) ----------------
__global__ __launch_bounds__(256) void star_attn_k(
    const float* __restrict__ qkv, float* __restrict__ attr)
{
    __shared__ float sq[HDIM];
    __shared__ float sc[NLP1];
    __shared__ float red[8];
    __shared__ float part[4][HDIM];
    int b = blockIdx.x >> 3, h = blockIdx.x & 7;
    int tid = threadIdx.x;
    size_t hb = (size_t)b * NLP1 * QS + (size_t)h * HDIM;
    if (tid < HDIM) sq[tid] = qkv[hb + (size_t)NL * QS + tid];   // relay q
    __syncthreads();
    float lmax = -1e30f;
    for (int l = tid; l < NLP1; l += 256) {
        const float4* kp = (const float4*)(qkv + hb + 512 + (size_t)l * QS);
        float d = 0.f;
#pragma unroll
        for (int j = 0; j < HDIM / 4; j++) {
            float4 kk = kp[j];
            d += sq[4 * j + 0] * kk.x + sq[4 * j + 1] * kk.y
               + sq[4 * j + 2] * kk.z + sq[4 * j + 3] * kk.w;
        }
        d *= 0.125f;
        sc[l] = d;
        lmax = fmaxf(lmax, d);
    }
    int lane = tid & 31, w = tid >> 5;
#pragma unroll
    for (int o = 16; o; o >>= 1) lmax = fmaxf(lmax, __shfl_xor_sync(0xffffffffu, lmax, o));
    if (lane == 0) red[w] = lmax;
    __syncthreads();
    if (tid == 0) {
        float m = red[0];
#pragma unroll
        for (int i = 1; i < 8; i++) m = fmaxf(m, red[i]);
        red[0] = m;
    }
    __syncthreads();
    float m = red[0];
    __syncthreads();
    float lsum = 0.f;
    for (int l = tid; l < NLP1; l += 256) {
        float e = __expf(sc[l] - m);
        sc[l] = e;
        lsum += e;
    }
#pragma unroll
    for (int o = 16; o; o >>= 1) lsum += __shfl_xor_sync(0xffffffffu, lsum, o);
    if (lane == 0) red[w] = lsum;
    __syncthreads();
    if (tid == 0) {
        float s = 0.f;
#pragma unroll
        for (int i = 0; i < 8; i++) s += red[i];
        red[0] = s;
    }
    __syncthreads();
    float Zinv = 1.f / red[0];
    int d = tid & 63, g = tid >> 6;
    float acc = 0.f;
    for (int l = g; l < NLP1; l += 4)
        acc += sc[l] * qkv[hb + 1024 + (size_t)l * QS + d];
    part[g][d] = acc;
    __syncthreads();
    if (tid < HDIM)
        attr[(size_t)b * NH + h * HDIM + tid] =
            (part[0][tid] + part[1][tid] + part[2][tid] + part[3][tid]) * Zinv;
}

// ---------------- star output GEMM + leaky (widened: 64 blocks) -------------
__global__ __launch_bounds__(256) void star_out_k(
    const float* __restrict__ attr, const float* __restrict__ w,
    const float* __restrict__ bias, float* __restrict__ relay)
{
    __shared__ float sa[512];
    __shared__ float red[4][64];
    int b = blockIdx.y, cx = blockIdx.x;
    int t = threadIdx.x;
    sa[t]       = attr[b * NH + t];
    sa[t + 256] = attr[b * NH + t + 256];
    __syncthreads();
    int col = cx * 64 + (t & 63), g = t >> 6;
    float acc = 0.f;
    const float* wp = w + (size_t)(g * 128) * NH + col;
#pragma unroll 4
    for (int kk = 0; kk < 128; kk++)
        acc += sa[g * 128 + kk] * wp[(size_t)kk * NH];
    red[g][t & 63] = acc;
    __syncthreads();
    if (t < 64) {
        float a = red[0][t] + red[1][t] + red[2][t] + red[3][t] + bias[cx * 64 + t];
        relay[b * NH + cx * 64 + t] = a > 0.f ? a : 0.2f * a;
    }
}

// ---------------- final max, two-phase ----------------
__global__ void final_part_k(const float* __restrict__ nodes, float* __restrict__ part)
{
    int b = blockIdx.y, ch = blockIdx.x, j = threadIdx.x;
    const float* p = nodes + ((size_t)b * NL + ch * 64) * NH + j;
    float m = -3.4e38f;
#pragma unroll 8
    for (int l = 0; l < 64; l++) m = fmaxf(m, p[(size_t)l * NH]);
    part[((size_t)b * 32 + ch) * NH + j] = m;
}
__global__ void final_fin_k(const float* __restrict__ part,
                            const float* __restrict__ relay, float* __restrict__ out)
{
    int b = blockIdx.x, j = threadIdx.x;
    float m = -3.4e38f;
#pragma unroll
    for (int c = 0; c < 32; c++) m = fmaxf(m, part[((size_t)b * 32 + c) * NH + j]);
    out[b * NH + j] = 0.5f * (relay[b * NH + j] + m);
}

// =====================================================================
//  host launch
// =====================================================================
extern "C" void kernel_launch(void* const* d_in, const int* in_sizes, int n_in,
                              void* d_out, int out_size)
{
    const float* data    = (const float*)d_in[0];
    const float* fc_w    = (const float*)d_in[1];
    const float* fc_b    = (const float*)d_in[2];
    const float* pos_emb = (const float*)d_in[3];
    const float* ln_g    = (const float*)d_in[4];
    const float* ln_b    = (const float*)d_in[5];
    const float* wq      = (const float*)d_in[6];
    const float* wk      = (const float*)d_in[7];
    const float* wv      = (const float*)d_in[8];
    const float* bq      = (const float*)d_in[9];
    const float* bk      = (const float*)d_in[10];
    const float* bv      = (const float*)d_in[11];
    const float* ring_wo = (const float*)d_in[12];
    const float* ring_bo = (const float*)d_in[13];
    const float* star_wo = (const float*)d_in[14];
    const float* star_bo = (const float*)d_in[15];
    float* out = (float*)d_out;

    float *nodes, *xy, *qkv, *att, *a32, *b32, *relay, *attr, *part;
    cudaGetSymbolAddress((void**)&nodes, g_nodes);
    cudaGetSymbolAddress((void**)&xy,    g_xy);
    cudaGetSymbolAddress((void**)&qkv,   g_qkv);
    cudaGetSymbolAddress((void**)&att,   g_att);
    cudaGetSymbolAddress((void**)&a32,   g_a32);
    cudaGetSymbolAddress((void**)&b32,   g_b32);
    cudaGetSymbolAddress((void**)&relay, g_relay);
    cudaGetSymbolAddress((void**)&attr,  g_attr);
    cudaGetSymbolAddress((void**)&part,  g_part);

    // one-time resources (streams/events are not device-memory allocations)
    static bool init_done = false;
    static cudaStream_t s2;
    static cudaEvent_t evFork[NLAYERS], evJoin[NLAYERS];
    if (!init_done) {
        cudaFuncSetAttribute(mmagemm32<0>, cudaFuncAttributeMaxDynamicSharedMemorySize, SMEM_GEMM);
        cudaFuncSetAttribute(mmagemm32<1>, cudaFuncAttributeMaxDynamicSharedMemorySize, SMEM_GEMM);
        cudaFuncSetAttribute(mmagemm32<2>, cudaFuncAttributeMaxDynamicSharedMemorySize, SMEM_GEMM);
        cudaStreamCreateWithFlags(&s2, cudaStreamNonBlocking);
        for (int i = 0; i < NLAYERS; i++) {
            cudaEventCreateWithFlags(&evFork[i], cudaEventDisableTiming);
            cudaEventCreateWithFlags(&evJoin[i], cudaEventDisableTiming);
        }
        init_done = true;
    }
    cudaStream_t s0 = (cudaStream_t)0;

    const int M_nodes = NB * NL;     // 16384
    const int M_xy    = NB * NLP1;   // 16392
    dim3 gN(4, M_nodes / 128);       // (4,128)  N=512
    dim3 gQKV(12, (M_xy + 127) / 128); // (12,129) N=1536

    // ---- all weight conversions in one launch ----
    convB_all_k<<<dim3(16, 16, 1 + NLAYERS * 4), 256>>>(fc_w, wq, wk, wv, ring_wo, b32);

    // ---- embeddings ----
    convA32_k<<<(M_nodes * 128 + 255) / 256, 256>>>(data, a32, M_nodes * 128);
    mmagemm32<0><<<gN, 256, SMEM_GEMM>>>(a32, b32, fc_b, fc_b, fc_b, pos_emb,
                                         nodes, M_nodes, NH);
    relay_part_k<<<dim3(32, NB), NH>>>(nodes, part);
    relay_fin_k<<<NB, NH>>>(part, relay);

    for (int i = 0; i < NLAYERS; i++) {
        size_t bOff = (size_t)i * 512;
        float* slot  = b32 + (size_t)(512 + i * 2048) * NH;
        float* slotO = slot + (size_t)1536 * NH;

        if (i > 0) cudaStreamWaitEvent(s0, evJoin[i - 1], 0);  // relay ready
        ln_concat_k<<<NB * NLP1, 256>>>(nodes, relay, ln_g + bOff, ln_b + bOff, xy);

        mmagemm32<1><<<gQKV, 256, SMEM_GEMM>>>(xy, slot, bq + bOff, bk + bOff,
                                               bv + bOff, nullptr, qkv, M_xy, QS);

        // fork: star branch on s2 (depends only on qkv), overlaps ring branch
        cudaEventRecord(evFork[i], s0);
        cudaStreamWaitEvent(s2, evFork[i], 0);
        star_attn_k<<<NB * NHEADS, 256, 0, s2>>>(qkv, attr);
        star_out_k<<<dim3(8, NB), 256, 0, s2>>>(attr, star_wo + (size_t)i * 512 * 512,
                                                star_bo + bOff, relay);
        cudaEventRecord(evJoin[i], s2);

        ring_attn_k<<<NB * NL * NHEADS / 8, 256>>>(qkv, att);
        mmagemm32<2><<<gN, 256, SMEM_GEMM>>>(att, slotO, ring_bo + bOff, ring_bo + bOff,
                                             ring_bo + bOff, nullptr, nodes, M_nodes, NH);
    }

    final_part_k<<<dim3(32, NB), NH>>>(nodes, part);
    cudaStreamWaitEvent(s0, evJoin[NLAYERS - 1], 0);           // relay ready
    final_fin_k<<<NB, NH>>>(part, relay, out);
}

// round 7
// speedup vs baseline: 6.0362x; 1.4897x over previous
#include <cuda_runtime.h>
#include <cuda_fp16.h>
#include <math.h>
#include <stdint.h>

// ---------------- problem constants ----------------
#define NB 8
#define NL 2048
#define NLP1 2049
#define NH 512
#define NHEADS 8
#define HDIM 64
#define NLAYERS 4

#define MPAD 16512          // 129*128 row capacity (A padding for cp.async)
#define QS 1536             // fused qkv row stride

// ---------------- scratch (device globals; no allocation) ----------------
__device__ float g_nodes[(size_t)NB * NL * NH];            // 32 MB
__device__ float g_qkv [(size_t)NB * NLP1 * QS];           // 100 MB
__device__ float g_relay[NB * NH];
__device__ float g_attr [NB * NH];
__device__ float g_part [(size_t)NB * 32 * NH];
__device__ __align__(16) __half g_a16[(size_t)MPAD * NH];  // 16.9 MB (GEMM A operand)
__device__ __align__(16) __half g_b16[(size_t)(512 + NLAYERS * 2048) * NH]; // 8.9 MB

// =====================================================================
//  low-level helpers
// =====================================================================
__device__ __forceinline__ uint32_t smem_u32(const void* p) {
    uint32_t a;
    asm("{ .reg .u64 t; cvta.to.shared.u64 t, %1; cvt.u32.u64 %0, t; }"
        : "=r"(a) : "l"(p));
    return a;
}

#define CP_ASYNC16(dst, src) \
    asm volatile("cp.async.cg.shared.global [%0], [%1], 16;" \
        :: "r"(dst), "l"(src) : "memory")
#define CP_COMMIT() asm volatile("cp.async.commit_group;" ::: "memory")
#define CP_WAIT(n)  asm volatile("cp.async.wait_group %0;" :: "n"(n) : "memory")

__device__ __forceinline__ void ldsm4(uint32_t* r, uint32_t addr) {
    asm volatile("ldmatrix.sync.aligned.m8n8.x4.shared.b16 {%0,%1,%2,%3}, [%4];"
        : "=r"(r[0]), "=r"(r[1]), "=r"(r[2]), "=r"(r[3]) : "r"(addr));
}

__device__ __forceinline__ void mma16816f(float* c, const uint32_t* a, const uint32_t* b) {
    asm volatile("mma.sync.aligned.m16n8k16.row.col.f32.f16.f16.f32 "
        "{%0,%1,%2,%3}, {%4,%5,%6,%7}, {%8,%9}, {%0,%1,%2,%3};"
        : "+f"(c[0]), "+f"(c[1]), "+f"(c[2]), "+f"(c[3])
        : "r"(a[0]), "r"(a[1]), "r"(a[2]), "r"(a[3]), "r"(b[0]), "r"(b[1]));
}

// swizzled byte offset within one stage tile: 128 rows x 64B (4 chunks of 16B)
__device__ __forceinline__ uint32_t swz(int row, int chunk) {
    return (uint32_t)(row * 64 + ((chunk ^ ((row >> 1) & 3)) << 4));
}

// =====================================================================
//  fp16 mma.sync GEMM: C[M, CS-cols] = A[M,512] @ Bt[N,512]^T + epilogue
//  tile 128x128, 8 warps (4M x 2N), kblock 32 (fp16: 64B rows), 4-stage
//  cp.async. Bias selected per 512-col segment (QKV fusion).
//  EPI 0: +bias +pos_emb ; 1: +bias ; 2: leaky(+bias)
// =====================================================================
#define STG 4
#define STAGE_BYTES 8192                 // 128 rows * 64B  (= K-chunk of 32 fp16)
#define SMEM_GEMM (2 * STG * STAGE_BYTES) // 64KB
#define KBLKS 16                          // 512 / 32

template<int EPI>
__global__ void __launch_bounds__(256, 2)
mmagemm16(const __half* __restrict__ A, const __half* __restrict__ Bt,
          const float* __restrict__ b0p, const float* __restrict__ b1p,
          const float* __restrict__ b2p, const float* __restrict__ extra,
          float* __restrict__ C, int M, int CS)
{
    extern __shared__ char smem[];
    const uint32_t aBase = smem_u32(smem);
    const uint32_t bBase = aBase + STG * STAGE_BYTES;
    const int tid = threadIdx.x, wid = tid >> 5, lane = tid & 31;
    const int nt = blockIdx.x, mt = blockIdx.y;
    const int warpM = wid & 3, warpN = wid >> 2;

    // loader mapping: thread -> (rows lrow, lrow+64 ; 16B chunk lch)
    const int lrow = tid >> 2, lch = tid & 3;
    const __half* ag0 = A + (size_t)(mt * 128 + lrow) * NH + lch * 8;
    const __half* bg0 = Bt + (size_t)(nt * 128 + lrow) * NH + lch * 8;
    const uint32_t sA0 = swz(lrow, lch), sA1 = swz(lrow + 64, lch);

#define LOAD_STAGE(kb, stg) do { \
    const __half* _ag = ag0 + (kb) * 32; \
    const __half* _bg = bg0 + (kb) * 32; \
    uint32_t _da = aBase + (stg) * STAGE_BYTES; \
    uint32_t _db = bBase + (stg) * STAGE_BYTES; \
    CP_ASYNC16(_da + sA0, _ag); \
    CP_ASYNC16(_da + sA1, _ag + (size_t)64 * NH); \
    CP_ASYNC16(_db + sA0, _bg); \
    CP_ASYNC16(_db + sA1, _bg + (size_t)64 * NH); \
    CP_COMMIT(); \
} while (0)

    LOAD_STAGE(0, 0);
    LOAD_STAGE(1, 1);
    LOAD_STAGE(2, 2);

    // ldmatrix per-lane bases (proven in R3 bf16 kernel)
    const int lr = lane & 7;
    const int aRowB = warpM * 32 + lr + ((lane >> 3) & 1) * 8;   // + mi*16
    const int aChB  = (lane >> 4);                               // + ks*2
    const int bRowB = warpN * 64 + lr + (lane >> 4) * 8;         // + p*16
    const int bChB  = (lane >> 3) & 1;                           // + ks*2

    float acc[64];
#pragma unroll
    for (int i = 0; i < 64; i++) acc[i] = 0.f;

    for (int kb = 0; kb < KBLKS; kb++) {
        const int stg = kb & 3;
        CP_WAIT(2);
        __syncthreads();
        if (kb + 3 < KBLKS) LOAD_STAGE(kb + 3, (kb + 3) & 3);

        const uint32_t da = aBase + stg * STAGE_BYTES;
        const uint32_t db = bBase + stg * STAGE_BYTES;
#pragma unroll
        for (int ks = 0; ks < 2; ks++) {
            uint32_t af[2][4];
#pragma unroll
            for (int mi = 0; mi < 2; mi++)
                ldsm4(af[mi], da + swz(aRowB + mi * 16, ks * 2 + aChB));
#pragma unroll
            for (int p = 0; p < 4; p++) {
                uint32_t bf[4];
                ldsm4(bf, db + swz(bRowB + p * 16, ks * 2 + bChB));
#pragma unroll
                for (int mi = 0; mi < 2; mi++) {
                    mma16816f(&acc[(mi * 8 + 2 * p + 0) * 4], af[mi], bf + 0);
                    mma16816f(&acc[(mi * 8 + 2 * p + 1) * 4], af[mi], bf + 2);
                }
            }
        }
        __syncthreads();
    }

    // epilogue
#pragma unroll
    for (int mi = 0; mi < 2; mi++) {
#pragma unroll
        for (int ntile = 0; ntile < 8; ntile++) {
            const float* c = &acc[(mi * 8 + ntile) * 4];
            int row0 = mt * 128 + warpM * 32 + mi * 16 + (lane >> 2);
            int col  = nt * 128 + warpN * 64 + ntile * 8 + (lane & 3) * 2;
            int seg = col >> 9;
            const float* bp = (seg == 0) ? b0p : (seg == 1) ? b1p : b2p;
            int cl = col & 511;
            float bb0 = bp[cl], bb1 = bp[cl + 1];
#pragma unroll
            for (int half0 = 0; half0 < 2; half0++) {
                int row = row0 + half0 * 8;
                if (row >= M) continue;
                float2 o;
                o.x = c[half0 * 2 + 0] + bb0;
                o.y = c[half0 * 2 + 1] + bb1;
                if (EPI == 0) {
                    const float* e = extra + (size_t)(row & (NL - 1)) * NH + col;
                    o.x += e[0]; o.y += e[1];
                }
                if (EPI == 2) {
                    o.x = o.x > 0.f ? o.x : 0.2f * o.x;
                    o.y = o.y > 0.f ? o.y : 0.2f * o.y;
                }
                *(float2*)(C + (size_t)row * CS + col) = o;
            }
        }
    }
#undef LOAD_STAGE
}

// ---------------- A conversion: fp32 -> fp16 (for `data` only) --------------
__global__ __launch_bounds__(256) void convA16_k(const float* __restrict__ in,
                                                 __half* __restrict__ out, int n4)
{
    int i = blockIdx.x * 256 + threadIdx.x;
    if (i >= n4) return;
    float4 x = ((const float4*)in)[i];
    __half2 h0 = __floats2half2_rn(x.x, x.y);
    __half2 h1 = __floats2half2_rn(x.z, x.w);
    ((__half2*)out)[i * 2]     = h0;
    ((__half2*)out)[i * 2 + 1] = h1;
}

// ---------------- ALL weight transposes -> fp16 in ONE launch ---------------
// slot z: 0 = fc_w -> b16[0]; z=1+i*4+j: layer i, j in {q,k,v,o}
__global__ __launch_bounds__(256) void convB_all_k(
    const float* __restrict__ fc_w, const float* __restrict__ wq,
    const float* __restrict__ wk,   const float* __restrict__ wv,
    const float* __restrict__ wo,   __half* __restrict__ b16)
{
    __shared__ float t[32][33];
    int s = blockIdx.z;
    const float* W;
    __half* Bt;
    if (s == 0) {
        W = fc_w; Bt = b16;
    } else {
        int i = (s - 1) >> 2, j = (s - 1) & 3;
        const float* src = (j == 0) ? wq : (j == 1) ? wk : (j == 2) ? wv : wo;
        W  = src + (size_t)i * NH * NH;
        Bt = b16 + (size_t)(512 + i * 2048 + j * 512) * NH;
    }
    int k0 = blockIdx.x * 32, n0 = blockIdx.y * 32;
    int tx = threadIdx.x & 31, ty = threadIdx.x >> 5;
#pragma unroll
    for (int i = 0; i < 32; i += 8)
        t[ty + i][tx] = W[(size_t)(k0 + ty + i) * NH + n0 + tx];
    __syncthreads();
#pragma unroll
    for (int i = 0; i < 32; i += 8) {
        int n = n0 + ty + i, k = k0 + tx;
        Bt[(size_t)n * NH + k] = __float2half_rn(t[tx][ty + i]);
    }
}

// ---------------- relay mean, two-phase ----------------
__global__ void relay_part_k(const float* __restrict__ embs, float* __restrict__ part)
{
    int b = blockIdx.y, ch = blockIdx.x, j = threadIdx.x;
    const float* p = embs + ((size_t)b * NL + ch * 64) * NH + j;
    float s = 0.f;
#pragma unroll 8
    for (int l = 0; l < 64; l++) s += p[(size_t)l * NH];
    part[((size_t)b * 32 + ch) * NH + j] = s;
}
__global__ void relay_fin_k(const float* __restrict__ part, float* __restrict__ relay)
{
    int b = blockIdx.x, j = threadIdx.x;
    float s = 0.f;
#pragma unroll
    for (int c = 0; c < 32; c++) s += part[((size_t)b * 32 + c) * NH + j];
    relay[b * NH + j] = s * (1.f / NL);
}

// ---------------- LayerNorm + concat relay -> a16 (fp16) --------------------
__global__ __launch_bounds__(256) void ln_concat_k(
    const float* __restrict__ nodes, const float* __restrict__ relay,
    const float* __restrict__ gamma, const float* __restrict__ beta,
    __half* __restrict__ a16)
{
    __shared__ float2 sh[8];
    int row = blockIdx.x;
    int b = row / NLP1, l = row - b * NLP1;
    int tid = threadIdx.x;
    __half2* dst = (__half2*)(a16 + (size_t)row * NH);

    if (l == NL) {
        float2 x = ((const float2*)(relay + b * NH))[tid];
        dst[tid] = __floats2half2_rn(x.x, x.y);
        return;
    }
    float2 x = ((const float2*)(nodes + ((size_t)b * NL + l) * NH))[tid];
    float2 v = make_float2(x.x + x.y, x.x * x.x + x.y * x.y);
    int lane = tid & 31, w = tid >> 5;
#pragma unroll
    for (int o = 16; o; o >>= 1) {
        v.x += __shfl_xor_sync(0xffffffffu, v.x, o);
        v.y += __shfl_xor_sync(0xffffffffu, v.y, o);
    }
    if (lane == 0) sh[w] = v;
    __syncthreads();
    if (tid == 0) {
        float2 t = sh[0];
#pragma unroll
        for (int i = 1; i < 8; i++) { t.x += sh[i].x; t.y += sh[i].y; }
        sh[0] = t;
    }
    __syncthreads();
    float2 t = sh[0];
    float mu = t.x * (1.f / NH);
    float var = t.y * (1.f / NH) - mu * mu;
    float inv = rsqrtf(var + 1e-6f);
    float2 g = ((const float2*)gamma)[tid];
    float2 bb = ((const float2*)beta)[tid];
    float ox = (x.x - mu) * inv * g.x + bb.x;
    float oy = (x.y - mu) * inv * g.y + bb.y;
    dst[tid] = __floats2half2_rn(ox, oy);
}

// ---------------- ring attention (reads fused qkv) -> a16 (fp16) ------------
__global__ __launch_bounds__(256) void ring_attn_k(
    const float* __restrict__ qkv, __half* __restrict__ a16)
{
    int gw = blockIdx.x * 8 + (threadIdx.x >> 5);
    int lane = threadIdx.x & 31;
    int h = gw & 7;
    int l = (gw >> 3) & (NL - 1);
    int b = gw >> 14;
    size_t rb = (size_t)b * NLP1 * QS + (size_t)h * HDIM + lane * 2;
    float2 qv = *(const float2*)(qkv + rb + (size_t)l * QS);

    const float* kk = qkv + rb + 512;
    const float* vv = qkv + rb + 1024;
    float2 z = make_float2(0.f, 0.f);
    float2 km = (l > 0)      ? *(const float2*)(kk + (size_t)(l - 1) * QS) : z;
    float2 kc =                *(const float2*)(kk + (size_t)l       * QS);
    float2 kp = (l < NL - 1) ? *(const float2*)(kk + (size_t)(l + 1) * QS) : z;
    float2 kr =                *(const float2*)(kk + (size_t)NL      * QS);
    float s0 = qv.x * km.x + qv.y * km.y;
    float s1 = qv.x * kc.x + qv.y * kc.y;
    float s2 = qv.x * kp.x + qv.y * kp.y;
    float s3 = qv.x * kr.x + qv.y * kr.y;
#pragma unroll
    for (int o = 16; o; o >>= 1) {
        s0 += __shfl_xor_sync(0xffffffffu, s0, o);
        s1 += __shfl_xor_sync(0xffffffffu, s1, o);
        s2 += __shfl_xor_sync(0xffffffffu, s2, o);
        s3 += __shfl_xor_sync(0xffffffffu, s3, o);
    }
    const float scale = 0.125f;
    s0 *= scale; s1 *= scale; s2 *= scale; s3 *= scale;
    float m = fmaxf(fmaxf(s0, s1), fmaxf(s2, s3));
    float e0 = __expf(s0 - m), e1 = __expf(s1 - m);
    float e2 = __expf(s2 - m), e3 = __expf(s3 - m);
    float inv = 1.f / (e0 + e1 + e2 + e3);
    float2 vm = (l > 0)      ? *(const float2*)(vv + (size_t)(l - 1) * QS) : z;
    float2 vc =                *(const float2*)(vv + (size_t)l       * QS);
    float2 vp = (l < NL - 1) ? *(const float2*)(vv + (size_t)(l + 1) * QS) : z;
    float2 vr =                *(const float2*)(vv + (size_t)NL      * QS);
    float ox = (e0 * vm.x + e1 * vc.x + e2 * vp.x + e3 * vr.x) * inv;
    float oy = (e0 * vm.y + e1 * vc.y + e2 * vp.y + e3 * vr.y) * inv;

    __half2* dst = (__half2*)(a16 + ((size_t)b * NL + l) * NH + (size_t)h * HDIM);
    dst[lane] = __floats2half2_rn(ox, oy);
}

// ---------------- star attention (reads fused qkv) ----------------
__global__ __launch_bounds__(256) void star_attn_k(
    const float* __restrict__ qkv, float* __restrict__ attr)
{
    __shared__ float sq[HDIM];
    __shared__ float sc[NLP1];
    __shared__ float red[8];
    __shared__ float part[4][HDIM];
    int b = blockIdx.x >> 3, h = blockIdx.x & 7;
    int tid = threadIdx.x;
    size_t hb = (size_t)b * NLP1 * QS + (size_t)h * HDIM;
    if (tid < HDIM) sq[tid] = qkv[hb + (size_t)NL * QS + tid];   // relay q
    __syncthreads();
    float lmax = -1e30f;
    for (int l = tid; l < NLP1; l += 256) {
        const float4* kp = (const float4*)(qkv + hb + 512 + (size_t)l * QS);
        float d = 0.f;
#pragma unroll
        for (int j = 0; j < HDIM / 4; j++) {
            float4 kk = kp[j];
            d += sq[4 * j + 0] * kk.x + sq[4 * j + 1] * kk.y
               + sq[4 * j + 2] * kk.z + sq[4 * j + 3] * kk.w;
        }
        d *= 0.125f;
        sc[l] = d;
        lmax = fmaxf(lmax, d);
    }
    int lane = tid & 31, w = tid >> 5;
#pragma unroll
    for (int o = 16; o; o >>= 1) lmax = fmaxf(lmax, __shfl_xor_sync(0xffffffffu, lmax, o));
    if (lane == 0) red[w] = lmax;
    __syncthreads();
    if (tid == 0) {
        float m = red[0];
#pragma unroll
        for (int i = 1; i < 8; i++) m = fmaxf(m, red[i]);
        red[0] = m;
    }
    __syncthreads();
    float m = red[0];
    __syncthreads();
    float lsum = 0.f;
    for (int l = tid; l < NLP1; l += 256) {
        float e = __expf(sc[l] - m);
        sc[l] = e;
        lsum += e;
    }
#pragma unroll
    for (int o = 16; o; o >>= 1) lsum += __shfl_xor_sync(0xffffffffu, lsum, o);
    if (lane == 0) red[w] = lsum;
    __syncthreads();
    if (tid == 0) {
        float s = 0.f;
#pragma unroll
        for (int i = 0; i < 8; i++) s += red[i];
        red[0] = s;
    }
    __syncthreads();
    float Zinv = 1.f / red[0];
    int d = tid & 63, g = tid >> 6;
    float acc = 0.f;
    for (int l = g; l < NLP1; l += 4)
        acc += sc[l] * qkv[hb + 1024 + (size_t)l * QS + d];
    part[g][d] = acc;
    __syncthreads();
    if (tid < HDIM)
        attr[(size_t)b * NH + h * HDIM + tid] =
            (part[0][tid] + part[1][tid] + part[2][tid] + part[3][tid]) * Zinv;
}

// ---------------- star output GEMM + leaky (widened: 64 blocks) -------------
__global__ __launch_bounds__(256) void star_out_k(
    const float* __restrict__ attr, const float* __restrict__ w,
    const float* __restrict__ bias, float* __restrict__ relay)
{
    __shared__ float sa[512];
    __shared__ float red[4][64];
    int b = blockIdx.y, cx = blockIdx.x;
    int t = threadIdx.x;
    sa[t]       = attr[b * NH + t];
    sa[t + 256] = attr[b * NH + t + 256];
    __syncthreads();
    int col = cx * 64 + (t & 63), g = t >> 6;
    float acc = 0.f;
    const float* wp = w + (size_t)(g * 128) * NH + col;
#pragma unroll 4
    for (int kk = 0; kk < 128; kk++)
        acc += sa[g * 128 + kk] * wp[(size_t)kk * NH];
    red[g][t & 63] = acc;
    __syncthreads();
    if (t < 64) {
        float a = red[0][t] + red[1][t] + red[2][t] + red[3][t] + bias[cx * 64 + t];
        relay[b * NH + cx * 64 + t] = a > 0.f ? a : 0.2f * a;
    }
}

// ---------------- final max, two-phase ----------------
__global__ void final_part_k(const float* __restrict__ nodes, float* __restrict__ part)
{
    int b = blockIdx.y, ch = blockIdx.x, j = threadIdx.x;
    const float* p = nodes + ((size_t)b * NL + ch * 64) * NH + j;
    float m = -3.4e38f;
#pragma unroll 8
    for (int l = 0; l < 64; l++) m = fmaxf(m, p[(size_t)l * NH]);
    part[((size_t)b * 32 + ch) * NH + j] = m;
}
__global__ void final_fin_k(const float* __restrict__ part,
                            const float* __restrict__ relay, float* __restrict__ out)
{
    int b = blockIdx.x, j = threadIdx.x;
    float m = -3.4e38f;
#pragma unroll
    for (int c = 0; c < 32; c++) m = fmaxf(m, part[((size_t)b * 32 + c) * NH + j]);
    out[b * NH + j] = 0.5f * (relay[b * NH + j] + m);
}

// =====================================================================
//  host launch
// =====================================================================
extern "C" void kernel_launch(void* const* d_in, const int* in_sizes, int n_in,
                              void* d_out, int out_size)
{
    const float* data    = (const float*)d_in[0];
    const float* fc_w    = (const float*)d_in[1];
    const float* fc_b    = (const float*)d_in[2];
    const float* pos_emb = (const float*)d_in[3];
    const float* ln_g    = (const float*)d_in[4];
    const float* ln_b    = (const float*)d_in[5];
    const float* wq      = (const float*)d_in[6];
    const float* wk      = (const float*)d_in[7];
    const float* wv      = (const float*)d_in[8];
    const float* bq      = (const float*)d_in[9];
    const float* bk      = (const float*)d_in[10];
    const float* bv      = (const float*)d_in[11];
    const float* ring_wo = (const float*)d_in[12];
    const float* ring_bo = (const float*)d_in[13];
    const float* star_wo = (const float*)d_in[14];
    const float* star_bo = (const float*)d_in[15];
    float* out = (float*)d_out;

    float *nodes, *qkv, *relay, *attr, *part;
    __half *a16, *b16;
    cudaGetSymbolAddress((void**)&nodes, g_nodes);
    cudaGetSymbolAddress((void**)&qkv,   g_qkv);
    cudaGetSymbolAddress((void**)&relay, g_relay);
    cudaGetSymbolAddress((void**)&attr,  g_attr);
    cudaGetSymbolAddress((void**)&part,  g_part);
    cudaGetSymbolAddress((void**)&a16,   g_a16);
    cudaGetSymbolAddress((void**)&b16,   g_b16);

    // one-time resources (streams/events are not device-memory allocations)
    static bool init_done = false;
    static cudaStream_t s2;
    static cudaEvent_t evFork[NLAYERS], evJoin[NLAYERS];
    if (!init_done) {
        cudaFuncSetAttribute(mmagemm16<0>, cudaFuncAttributeMaxDynamicSharedMemorySize, SMEM_GEMM);
        cudaFuncSetAttribute(mmagemm16<1>, cudaFuncAttributeMaxDynamicSharedMemorySize, SMEM_GEMM);
        cudaFuncSetAttribute(mmagemm16<2>, cudaFuncAttributeMaxDynamicSharedMemorySize, SMEM_GEMM);
        cudaStreamCreateWithFlags(&s2, cudaStreamNonBlocking);
        for (int i = 0; i < NLAYERS; i++) {
            cudaEventCreateWithFlags(&evFork[i], cudaEventDisableTiming);
            cudaEventCreateWithFlags(&evJoin[i], cudaEventDisableTiming);
        }
        init_done = true;
    }
    cudaStream_t s0 = (cudaStream_t)0;

    const int M_nodes = NB * NL;     // 16384
    const int M_xy    = NB * NLP1;   // 16392
    dim3 gN(4, M_nodes / 128);       // (4,128)  N=512
    dim3 gQKV(12, (M_xy + 127) / 128); // (12,129) N=1536

    // ---- all weight conversions in one launch ----
    convB_all_k<<<dim3(16, 16, 1 + NLAYERS * 4), 256>>>(fc_w, wq, wk, wv, ring_wo, b16);

    // ---- embeddings ----
    convA16_k<<<(M_nodes * 128 + 255) / 256, 256>>>(data, a16, M_nodes * 128);
    mmagemm16<0><<<gN, 256, SMEM_GEMM>>>(a16, b16, fc_b, fc_b, fc_b, pos_emb,
                                         nodes, M_nodes, NH);
    relay_part_k<<<dim3(32, NB), NH>>>(nodes, part);
    relay_fin_k<<<NB, NH>>>(part, relay);

    for (int i = 0; i < NLAYERS; i++) {
        size_t bOff = (size_t)i * 512;
        __half* slot  = b16 + (size_t)(512 + i * 2048) * NH;
        __half* slotO = slot + (size_t)1536 * NH;

        if (i > 0) cudaStreamWaitEvent(s0, evJoin[i - 1], 0);  // relay ready
        ln_concat_k<<<NB * NLP1, 256>>>(nodes, relay, ln_g + bOff, ln_b + bOff, a16);

        mmagemm16<1><<<gQKV, 256, SMEM_GEMM>>>(a16, slot, bq + bOff, bk + bOff,
                                               bv + bOff, nullptr, qkv, M_xy, QS);

        // fork: star branch on s2 (depends only on qkv), overlaps ring branch
        cudaEventRecord(evFork[i], s0);
        cudaStreamWaitEvent(s2, evFork[i], 0);
        star_attn_k<<<NB * NHEADS, 256, 0, s2>>>(qkv, attr);
        star_out_k<<<dim3(8, NB), 256, 0, s2>>>(attr, star_wo + (size_t)i * 512 * 512,
                                                star_bo + bOff, relay);
        cudaEventRecord(evJoin[i], s2);

        ring_attn_k<<<NB * NL * NHEADS / 8, 256>>>(qkv, a16);
        mmagemm16<2><<<gN, 256, SMEM_GEMM>>>(a16, slotO, ring_bo + bOff, ring_bo + bOff,
                                             ring_bo + bOff, nullptr, nodes, M_nodes, NH);
    }

    final_part_k<<<dim3(32, NB), NH>>>(nodes, part);
    cudaStreamWaitEvent(s0, evJoin[NLAYERS - 1], 0);           // relay ready
    final_fin_k<<<NB, NH>>>(part, relay, out);
}